// round 7
// baseline (speedup 1.0000x reference)
#include <cuda_runtime.h>
#include <cuda_bf16.h>
#include <math.h>

// Fixed problem shape (from setup_inputs): N=100000, E=1600000, F_IN=128, H=C=64
#define NNODES 100000
#define HD 64
#define MSGMAX 1800000   // E + N with headroom

// Scratch (allocation-free: __device__ globals)
__device__ int       g_cnt[NNODES];         // per-dst message count (incl. self-loop)
__device__ int       g_off[NNODES + 1];     // CSR offsets
__device__ int       g_cur[NNODES];         // placement cursors
__device__ long long g_desc[512];           // lookback descriptors {flag,val}
__device__ float2    g_rec[MSGMAX];         // per-message {src_bits, norm}
__device__ uint4     g_h[NNODES * 8];       // layer-1 GEMM output, bf16 (8 uint4/row)
__device__ uint4     g_h2[NNODES * 8];      // layer-2 fused output, bf16 (separate:
                                            // fused kernel gathers g_h while writing)
__device__ int       g_is64;                // edge_index dtype flag

__device__ __forceinline__ long long load_edge(const void* ei, long long pos) {
    if (g_is64) return ((const long long*)ei)[pos];
    return (long long)((const int*)ei)[pos];
}

__device__ __forceinline__ void ffma2(unsigned long long& d, unsigned long long a,
                                      unsigned long long b) {
    asm("fma.rn.f32x2 %0, %1, %2, %0;" : "+l"(d) : "l"(a), "l"(b));
}

// ---------------------------------------------------------------------------
// init: cnt = 1 (self loop), zero lookback descriptors, detect index width
// ---------------------------------------------------------------------------
__global__ void k_init(const void* ei, int N) {
    int i = blockIdx.x * 256 + threadIdx.x;
    if (i < N) g_cnt[i] = 1;
    if (i < 512) g_desc[i] = 0;
    if (i == 0) {
        const unsigned long long* p = (const unsigned long long*)ei;
        int ok = 1;
        #pragma unroll 4
        for (int j = 0; j < 64; j++)
            if (p[j] >= (unsigned long long)N) ok = 0;
        g_is64 = ok;
    }
}

// ---------------------------------------------------------------------------
// degree count over dst
// ---------------------------------------------------------------------------
__global__ void k_count(const void* ei, long long E) {
    long long e = (long long)blockIdx.x * 256 + threadIdx.x;
    if (e < E) {
        int d = (int)load_edge(ei, E + e);
        atomicAdd(&g_cnt[d], 1);
    }
}

// ---------------------------------------------------------------------------
// Single-pass exclusive scan of g_cnt -> g_off/g_cur via decoupled lookback.
// 391 blocks of 256 all fit in one wave (no deadlock). Descriptor is a packed
// 64-bit {flag<<32 | value} read/written atomically. flag: 1=agg, 2=prefix.
// ---------------------------------------------------------------------------
__global__ void k_scan(int N) {
    __shared__ int s[256];
    __shared__ int sbase;
    int b = blockIdx.x, tid = threadIdx.x;
    int i = b * 256 + tid;
    int v = (i < N) ? g_cnt[i] : 0;
    s[tid] = v;
    __syncthreads();
    #pragma unroll
    for (int o = 1; o < 256; o <<= 1) {
        int tv = (tid >= o) ? s[tid - o] : 0;
        __syncthreads();
        s[tid] += tv;
        __syncthreads();
    }
    int incl = s[tid];
    int bsum = s[255];

    volatile long long* desc = (volatile long long*)g_desc;
    if (tid == 0) {
        if (b == 0) { desc[0] = (2LL << 32) | (unsigned)bsum; sbase = 0; }
        else        { desc[b] = (1LL << 32) | (unsigned)bsum; }
    }
    if (b > 0 && tid < 32) {
        int lane = tid;
        int base = 0;
        int j = b - 1;
        while (true) {
            int idx = j - lane;
            int f = 0, val = 0;
            if (idx >= 0) {
                long long dsc;
                do { dsc = desc[idx]; } while ((int)(dsc >> 32) == 0);
                f = (int)(dsc >> 32);
                val = (int)(unsigned)dsc;
            }
            unsigned pm = __ballot_sync(0xffffffffu, f == 2);
            if (pm) {
                int firstLane = __ffs(pm) - 1;   // largest idx with a prefix
                int contrib = (lane <= firstLane) ? val : 0;
                #pragma unroll
                for (int o = 16; o > 0; o >>= 1)
                    contrib += __shfl_xor_sync(0xffffffffu, contrib, o);
                base += contrib;
                break;
            } else {
                int contrib = val;
                #pragma unroll
                for (int o = 16; o > 0; o >>= 1)
                    contrib += __shfl_xor_sync(0xffffffffu, contrib, o);
                base += contrib;
                j -= 32;
            }
        }
        if (lane == 0) {
            desc[b] = (2LL << 32) | (unsigned)(base + bsum);
            sbase = base;
        }
    }
    __syncthreads();
    int base = sbase;
    if (i < N) {
        int off = base + incl - v;   // exclusive
        g_off[i] = off;
        g_cur[i] = off;
        if (i == N - 1) g_off[N] = off + v;
    }
}

// ---------------------------------------------------------------------------
// place: bucket message records {src, rsqrt(deg_s*deg_d)} by dst
// ---------------------------------------------------------------------------
__global__ void k_place(const void* ei, long long E, int N) {
    long long e = (long long)blockIdx.x * 256 + threadIdx.x;
    long long M = E + (long long)N;
    if (e >= M) return;
    int s, d;
    if (e < E) {
        s = (int)load_edge(ei, e);
        d = (int)load_edge(ei, E + e);
    } else {
        s = d = (int)(e - E);
    }
    float nrm = rsqrtf((float)(g_cnt[s] * g_cnt[d]));
    int pos = atomicAdd(&g_cur[d], 1);
    g_rec[pos] = make_float2(__int_as_float(s), nrm);
}

// ---------------------------------------------------------------------------
// GEMM1: out[N,64](bf16) = X[N,128] @ W[K,64].  FFMA2 core.
// ---------------------------------------------------------------------------
template <int K>
__global__ __launch_bounds__(256, 2)
void k_gemm(const float* __restrict__ X, const float* __restrict__ W,
            uint2* __restrict__ out, int N) {
    const int KT = 32;
    const int XS = 68;
    __shared__ float Ws[KT * 64];
    __shared__ float Xs[128 * XS];

    int tid = threadIdx.x;
    int cg = tid & 15;
    int rg = tid >> 4;
    int row0 = blockIdx.x * 128;

    unsigned long long axy[8], azw[8];
    #pragma unroll
    for (int j = 0; j < 8; j++) { axy[j] = 0ull; azw[j] = 0ull; }

    for (int kt = 0; kt < K; kt += KT) {
        __syncthreads();
        {
            const float4* Wg = (const float4*)W + (long long)kt * 16;
            float4* Wt = (float4*)Ws;
            Wt[tid]       = Wg[tid];
            Wt[tid + 256] = Wg[tid + 256];
        }
        #pragma unroll
        for (int i = 0; i < 4; i++) {
            int idx = i * 256 + tid;
            int r  = idx >> 3;
            int kq = idx & 7;
            int gr = row0 + r;
            float4 v = make_float4(0.f, 0.f, 0.f, 0.f);
            if (gr < N)
                v = *(const float4*)(X + (long long)gr * K + kt + kq * 4);
            float* p = Xs + r * XS + kq * 8;
            *(float2*)(p + 0) = make_float2(v.x, v.x);
            *(float2*)(p + 2) = make_float2(v.y, v.y);
            *(float2*)(p + 4) = make_float2(v.z, v.z);
            *(float2*)(p + 6) = make_float2(v.w, v.w);
        }
        __syncthreads();

        const float* Xr = Xs + (rg * 8) * XS;
        #pragma unroll
        for (int kk = 0; kk < KT / 2; kk++) {
            unsigned long long w0xy = *(const unsigned long long*)(Ws + (2 * kk) * 64 + cg * 4);
            unsigned long long w0zw = *(const unsigned long long*)(Ws + (2 * kk) * 64 + cg * 4 + 2);
            unsigned long long w1xy = *(const unsigned long long*)(Ws + (2 * kk + 1) * 64 + cg * 4);
            unsigned long long w1zw = *(const unsigned long long*)(Ws + (2 * kk + 1) * 64 + cg * 4 + 2);
            #pragma unroll
            for (int j = 0; j < 8; j++) {
                ulonglong2 xd = *(const ulonglong2*)(Xr + j * XS + kk * 4);
                ffma2(axy[j], xd.x, w0xy);
                ffma2(azw[j], xd.x, w0zw);
                ffma2(axy[j], xd.y, w1xy);
                ffma2(azw[j], xd.y, w1zw);
            }
        }
    }

    #pragma unroll
    for (int j = 0; j < 8; j++) {
        int gr = row0 + rg * 8 + j;
        if (gr < N) {
            float2 lo = *(float2*)&axy[j];
            float2 hi = *(float2*)&azw[j];
            __nv_bfloat162 b0 = __float22bfloat162_rn(lo);
            __nv_bfloat162 b1 = __float22bfloat162_rn(hi);
            uint2 pk;
            pk.x = *(unsigned*)&b0;
            pk.y = *(unsigned*)&b1;
            out[(long long)gr * 16 + cg] = pk;
        }
    }
}

// ---------------------------------------------------------------------------
// FUSED layer 2: block handles 128 nodes.
// Phase 1: aggregate each node's CSR bucket (bf16 gather from g_h, fp32 acc),
//          apply relu(+b1), stage rows in smem.
// Phase 2: GEMM K=64 from staging smem; bf16 store to SEPARATE buffer g_h2
//          (g_h must stay immutable: other blocks still gather from it).
// ---------------------------------------------------------------------------
__global__ __launch_bounds__(256, 2)
void k_fuse(const uint4* __restrict__ h, const float* __restrict__ W,
            const float* __restrict__ bias, uint2* __restrict__ out, int N) {
    const int XS = 68;
    __shared__ float Xs[128 * XS];      // 34.8 KB staged rows
    __shared__ float Ws[32 * 64];       // 8 KB W tile

    int tid = threadIdx.x;
    int w = tid >> 5;
    int lane = tid & 31;
    int grp = lane >> 3;
    int gl  = lane & 7;
    int node0 = blockIdx.x * 128;

    float4 bb0 = __ldg((const float4*)bias + gl * 2);
    float4 bb1 = __ldg((const float4*)bias + gl * 2 + 1);

    // Phase 1: each warp aggregates 16 nodes (stride 8)
    for (int r = 0; r < 16; r++) {
        int nl = w + r * 8;
        int node = node0 + nl;
        if (node >= N) break;          // warp-uniform
        int beg = g_off[node];
        int end = g_off[node + 1];

        float2 acc[4];
        #pragma unroll
        for (int i = 0; i < 4; i++) acc[i] = make_float2(0.f, 0.f);

        #pragma unroll 2
        for (int j = beg + grp; j < end; j += 4) {
            float2 rc = g_rec[j];
            int s = __float_as_int(rc.x);
            uint4 v = __ldg(h + (long long)s * 8 + gl);
            float2 f;
            f = __bfloat1622float2(*(__nv_bfloat162*)&v.x);
            acc[0].x += f.x * rc.y; acc[0].y += f.y * rc.y;
            f = __bfloat1622float2(*(__nv_bfloat162*)&v.y);
            acc[1].x += f.x * rc.y; acc[1].y += f.y * rc.y;
            f = __bfloat1622float2(*(__nv_bfloat162*)&v.z);
            acc[2].x += f.x * rc.y; acc[2].y += f.y * rc.y;
            f = __bfloat1622float2(*(__nv_bfloat162*)&v.w);
            acc[3].x += f.x * rc.y; acc[3].y += f.y * rc.y;
        }
        #pragma unroll
        for (int i = 0; i < 4; i++) {
            acc[i].x += __shfl_xor_sync(0xffffffffu, acc[i].x, 8);
            acc[i].y += __shfl_xor_sync(0xffffffffu, acc[i].y, 8);
            acc[i].x += __shfl_xor_sync(0xffffffffu, acc[i].x, 16);
            acc[i].y += __shfl_xor_sync(0xffffffffu, acc[i].y, 16);
        }
        if (lane < 8) {
            float4 o0 = make_float4(fmaxf(acc[0].x + bb0.x, 0.f),
                                    fmaxf(acc[0].y + bb0.y, 0.f),
                                    fmaxf(acc[1].x + bb0.z, 0.f),
                                    fmaxf(acc[1].y + bb0.w, 0.f));
            float4 o1 = make_float4(fmaxf(acc[2].x + bb1.x, 0.f),
                                    fmaxf(acc[2].y + bb1.y, 0.f),
                                    fmaxf(acc[3].x + bb1.z, 0.f),
                                    fmaxf(acc[3].y + bb1.w, 0.f));
            *(float4*)(Xs + nl * XS + gl * 8)     = o0;
            *(float4*)(Xs + nl * XS + gl * 8 + 4) = o1;
        }
    }
    __syncthreads();

    // Phase 2: GEMM K=64 from staging
    int cg = tid & 15;
    int rg = tid >> 4;
    float4 acc[8];
    #pragma unroll
    for (int j = 0; j < 8; j++) acc[j] = make_float4(0.f, 0.f, 0.f, 0.f);

    for (int kt = 0; kt < 64; kt += 32) {
        if (kt) __syncthreads();
        {
            const float4* Wg = (const float4*)W + (long long)kt * 16;
            float4* Wt = (float4*)Ws;
            Wt[tid]       = Wg[tid];
            Wt[tid + 256] = Wg[tid + 256];
        }
        __syncthreads();
        const float4* Ws4 = (const float4*)Ws;
        #pragma unroll
        for (int k4 = 0; k4 < 8; k4++) {
            float4 w0 = Ws4[(k4 * 4 + 0) * 16 + cg];
            float4 w1 = Ws4[(k4 * 4 + 1) * 16 + cg];
            float4 w2 = Ws4[(k4 * 4 + 2) * 16 + cg];
            float4 w3 = Ws4[(k4 * 4 + 3) * 16 + cg];
            #pragma unroll
            for (int j = 0; j < 8; j++) {
                float4 xv = *(const float4*)(Xs + (rg * 8 + j) * XS + kt + k4 * 4);
                acc[j].x += xv.x * w0.x + xv.y * w1.x + xv.z * w2.x + xv.w * w3.x;
                acc[j].y += xv.x * w0.y + xv.y * w1.y + xv.z * w2.y + xv.w * w3.y;
                acc[j].z += xv.x * w0.z + xv.y * w1.z + xv.z * w2.z + xv.w * w3.z;
                acc[j].w += xv.x * w0.w + xv.y * w1.w + xv.z * w2.w + xv.w * w3.w;
            }
        }
    }

    #pragma unroll
    for (int j = 0; j < 8; j++) {
        int gr = node0 + rg * 8 + j;
        if (gr < N) {
            __nv_bfloat162 b0 = __float22bfloat162_rn(make_float2(acc[j].x, acc[j].y));
            __nv_bfloat162 b1 = __float22bfloat162_rn(make_float2(acc[j].z, acc[j].w));
            uint2 pk;
            pk.x = *(unsigned*)&b0;
            pk.y = *(unsigned*)&b1;
            out[(long long)gr * 16 + cg] = pk;
        }
    }
}

// ---------------------------------------------------------------------------
// Final aggregate from bf16 h2 + b2 + log_softmax -> fp32 output.
// ---------------------------------------------------------------------------
__global__ void k_agg_final(const uint4* __restrict__ h, float* __restrict__ out,
                            const float* __restrict__ bias, int N) {
    int node = blockIdx.x * 8 + (threadIdx.x >> 5);
    if (node >= N) return;
    int lane = threadIdx.x & 31;
    int grp = lane >> 3;
    int gl  = lane & 7;
    int beg = g_off[node];
    int end = g_off[node + 1];

    float2 acc[4];
    #pragma unroll
    for (int i = 0; i < 4; i++) acc[i] = make_float2(0.f, 0.f);

    #pragma unroll 2
    for (int j = beg + grp; j < end; j += 4) {
        float2 r = g_rec[j];
        int s = __float_as_int(r.x);
        uint4 v = __ldg(h + (long long)s * 8 + gl);
        float2 f;
        f = __bfloat1622float2(*(__nv_bfloat162*)&v.x);
        acc[0].x += f.x * r.y; acc[0].y += f.y * r.y;
        f = __bfloat1622float2(*(__nv_bfloat162*)&v.y);
        acc[1].x += f.x * r.y; acc[1].y += f.y * r.y;
        f = __bfloat1622float2(*(__nv_bfloat162*)&v.z);
        acc[2].x += f.x * r.y; acc[2].y += f.y * r.y;
        f = __bfloat1622float2(*(__nv_bfloat162*)&v.w);
        acc[3].x += f.x * r.y; acc[3].y += f.y * r.y;
    }
    #pragma unroll
    for (int i = 0; i < 4; i++) {
        acc[i].x += __shfl_xor_sync(0xffffffffu, acc[i].x, 8);
        acc[i].y += __shfl_xor_sync(0xffffffffu, acc[i].y, 8);
        acc[i].x += __shfl_xor_sync(0xffffffffu, acc[i].x, 16);
        acc[i].y += __shfl_xor_sync(0xffffffffu, acc[i].y, 16);
    }

    const float4* bp = (const float4*)(bias + gl * 8);
    float4 b0 = bp[0], b1 = bp[1];
    acc[0].x += b0.x; acc[0].y += b0.y; acc[1].x += b0.z; acc[1].y += b0.w;
    acc[2].x += b1.x; acc[2].y += b1.y; acc[3].x += b1.z; acc[3].y += b1.w;
    float m = fmaxf(fmaxf(fmaxf(acc[0].x, acc[0].y), fmaxf(acc[1].x, acc[1].y)),
                    fmaxf(fmaxf(acc[2].x, acc[2].y), fmaxf(acc[3].x, acc[3].y)));
    #pragma unroll
    for (int o = 1; o < 8; o <<= 1)
        m = fmaxf(m, __shfl_xor_sync(0xffffffffu, m, o));
    float s = expf(acc[0].x - m) + expf(acc[0].y - m)
            + expf(acc[1].x - m) + expf(acc[1].y - m)
            + expf(acc[2].x - m) + expf(acc[2].y - m)
            + expf(acc[3].x - m) + expf(acc[3].y - m);
    #pragma unroll
    for (int o = 1; o < 8; o <<= 1)
        s += __shfl_xor_sync(0xffffffffu, s, o);
    float lse = m + logf(s);
    if (lane < 8) {
        float4* op = (float4*)(out + (long long)node * 64 + gl * 8);
        op[0] = make_float4(acc[0].x - lse, acc[0].y - lse,
                            acc[1].x - lse, acc[1].y - lse);
        op[1] = make_float4(acc[2].x - lse, acc[2].y - lse,
                            acc[3].x - lse, acc[3].y - lse);
    }
}

// ---------------------------------------------------------------------------
extern "C" void kernel_launch(void* const* d_in, const int* in_sizes, int n_in,
                              void* d_out, int out_size) {
    const float* x  = (const float*)d_in[0];
    const void*  ei = d_in[1];
    const float* W1 = (const float*)d_in[2];
    const float* b1 = (const float*)d_in[3];
    const float* W2 = (const float*)d_in[4];
    const float* b2 = (const float*)d_in[5];
    float* out = (float*)d_out;

    int N = in_sizes[0] / 128;                 // 100000
    long long E = (long long)in_sizes[1] / 2;  // 1600000
    long long M = E + (long long)N;

    static cudaStream_t s2 = nullptr;
    static cudaEvent_t evFork = nullptr, evJoin = nullptr;
    if (!s2) {
        cudaStreamCreateWithFlags(&s2, cudaStreamNonBlocking);
        cudaEventCreateWithFlags(&evFork, cudaEventDisableTiming);
        cudaEventCreateWithFlags(&evJoin, cudaEventDisableTiming);
    }

    uint4 *ph, *ph2;
    cudaGetSymbolAddress((void**)&ph, g_h);
    cudaGetSymbolAddress((void**)&ph2, g_h2);

    int bN    = (N + 255) / 256;
    int bDeg  = (int)((E + 255) / 256);
    int bMsg  = (int)((M + 255) / 256);
    int bGemm = (N + 127) / 128;
    int bAgg  = (N + 7) / 8;

    // Fork: GEMM1 (x,W1 only) on s2, concurrent with CSR prep on capture stream.
    cudaEventRecord(evFork, 0);
    cudaStreamWaitEvent(s2, evFork, 0);
    k_gemm<128><<<bGemm, 256, 0, s2>>>(x, W1, (uint2*)ph, N);
    cudaEventRecord(evJoin, s2);

    k_init<<<bN, 256>>>(ei, N);
    k_count<<<bDeg, 256>>>(ei, E);
    k_scan<<<bN, 256>>>(N);
    k_place<<<bMsg, 256>>>(ei, E, N);

    // Join: fused layer-2 needs g_h (s2) and g_rec/g_off (default)
    cudaStreamWaitEvent(0, evJoin, 0);

    // fused: agg(layer1 from g_h) + relu+b1 + GEMM2 -> bf16 g_h2
    k_fuse<<<bGemm, 256>>>(ph, W2, b1, (uint2*)ph2, N);

    // final aggregate (from g_h2) + b2 + log_softmax
    k_agg_final<<<bAgg, 256>>>(ph2, out, b2, N);
}

// round 8
// speedup vs baseline: 1.0087x; 1.0087x over previous
#include <cuda_runtime.h>
#include <cuda_bf16.h>
#include <math.h>

// Fixed problem shape (from setup_inputs): N=100000, E=1600000, F_IN=128, H=C=64
#define NNODES 100000
#define HD 64
#define MSGMAX 1800000   // E + N with headroom

// Scratch (allocation-free: __device__ globals)
__device__ int       g_cnt[NNODES];         // per-dst message count (incl. self-loop)
__device__ int       g_off[NNODES + 1];     // CSR offsets
__device__ int       g_cur[NNODES];         // placement cursors
__device__ int       g_bsum[512];           // block sums for scan
__device__ float2    g_rec[MSGMAX];         // per-message {src_bits, norm}
__device__ uint4     g_h[NNODES * 8];       // bf16 h (8 uint4/row); reused for h2
__device__ float     g_agg[NNODES * HD];    // layer-1 aggregate (fp32)
__device__ int       g_is64;                // edge_index dtype flag

// software grid barrier state (gen is monotonic => replay-safe)
__device__ int               g_barcnt = 0;
__device__ volatile unsigned g_bargen = 0;

__device__ __forceinline__ void grid_bar(int nblocks) {
    __syncthreads();
    if (threadIdx.x == 0) {
        __threadfence();
        unsigned gen = g_bargen;
        if (atomicAdd(&g_barcnt, 1) == nblocks - 1) {
            g_barcnt = 0;
            __threadfence();
            g_bargen = gen + 1;
        } else {
            while (g_bargen == gen) { }
        }
    }
    __syncthreads();
    __threadfence();
}

__device__ __forceinline__ long long load_edge(const void* ei, long long pos) {
    if (g_is64) return ((const long long*)ei)[pos];
    return (long long)((const int*)ei)[pos];
}

__device__ __forceinline__ void ffma2(unsigned long long& d, unsigned long long a,
                                      unsigned long long b) {
    asm("fma.rn.f32x2 %0, %1, %2, %0;" : "+l"(d) : "l"(a), "l"(b));
}

// ---------------------------------------------------------------------------
// ONE-KERNEL CSR prep: init -> count -> scan -> place, separated by software
// grid barriers. 391 blocks (one wave); safe even co-running with GEMM1 on s2
// (GEMM1 never waits on prep, so prep blocks always get scheduled).
// ---------------------------------------------------------------------------
__global__ __launch_bounds__(256)
void k_prep(const void* ei, long long E, int N, int nb) {
    __shared__ int s[256];
    int tid = threadIdx.x;
    int b = blockIdx.x;
    int i = b * 256 + tid;
    long long stride = (long long)nb * 256;

    // phase A: init cnt=1 (self loop), detect index width
    if (i < N) g_cnt[i] = 1;
    if (i == 0) {
        const unsigned long long* p = (const unsigned long long*)ei;
        int ok = 1;
        #pragma unroll 4
        for (int j = 0; j < 64; j++)
            if (p[j] >= (unsigned long long)N) ok = 0;
        g_is64 = ok;
    }
    grid_bar(nb);

    // phase B: degree count over dst
    for (long long e = i; e < E; e += stride) {
        int d = (int)load_edge(ei, E + e);
        atomicAdd(&g_cnt[d], 1);
    }
    grid_bar(nb);

    // phase C: exclusive scan of g_cnt -> g_off/g_cur
    int v = (i < N) ? g_cnt[i] : 0;
    s[tid] = v;
    __syncthreads();
    #pragma unroll
    for (int o = 1; o < 256; o <<= 1) {
        int tv = (tid >= o) ? s[tid - o] : 0;
        __syncthreads();
        s[tid] += tv;
        __syncthreads();
    }
    int incl = s[tid];
    int bsum = s[255];
    if (tid == 0) g_bsum[b] = bsum;
    grid_bar(nb);

    int partial = 0;
    for (int j = tid; j < b; j += 256) partial += g_bsum[j];
    __syncthreads();
    s[tid] = partial;
    __syncthreads();
    #pragma unroll
    for (int o = 128; o > 0; o >>= 1) {
        if (tid < o) s[tid] += s[tid + o];
        __syncthreads();
    }
    int base = s[0];
    if (i < N) {
        int off = base + incl - v;     // exclusive
        g_off[i] = off;
        g_cur[i] = off;
        if (i == N - 1) g_off[N] = off + v;
    }
    grid_bar(nb);

    // phase D: place records {src, rsqrt(deg_s*deg_d)} bucketed by dst
    long long M = E + (long long)N;
    for (long long e = i; e < M; e += stride) {
        int sn, d;
        if (e < E) {
            sn = (int)load_edge(ei, e);
            d  = (int)load_edge(ei, E + e);
        } else {
            sn = d = (int)(e - E);
        }
        float nrm = rsqrtf((float)(g_cnt[sn] * g_cnt[d]));
        int pos = atomicAdd(&g_cur[d], 1);
        g_rec[pos] = make_float2(__int_as_float(sn), nrm);
    }
}

// ---------------------------------------------------------------------------
// GEMM: out[N,64](bf16) = act(X[N,K]) @ W[K,64]; act = relu(x+bias) if RELU_IN.
// CTA tile 128x64, 256 threads, thread tile 8x4, K tiled by 32, FFMA2 core.
// ---------------------------------------------------------------------------
template <int K, int RELU_IN>
__global__ __launch_bounds__(256, 2)
void k_gemm(const float* __restrict__ X, const float* __restrict__ W,
            const float* __restrict__ bias, uint2* __restrict__ out, int N) {
    const int KT = 32;
    const int XS = 68;
    __shared__ float Ws[KT * 64];
    __shared__ float Xs[128 * XS];
    __shared__ float bs[64];

    int tid = threadIdx.x;
    int cg = tid & 15;
    int rg = tid >> 4;
    int row0 = blockIdx.x * 128;

    if (RELU_IN && tid < 64) bs[tid] = bias[tid];

    unsigned long long axy[8], azw[8];
    #pragma unroll
    for (int j = 0; j < 8; j++) { axy[j] = 0ull; azw[j] = 0ull; }

    for (int kt = 0; kt < K; kt += KT) {
        __syncthreads();   // also orders bs before first X-tile use
        {
            const float4* Wg = (const float4*)W + (long long)kt * 16;
            float4* Wt = (float4*)Ws;
            Wt[tid]       = Wg[tid];
            Wt[tid + 256] = Wg[tid + 256];
        }
        #pragma unroll
        for (int i = 0; i < 4; i++) {
            int idx = i * 256 + tid;
            int r  = idx >> 3;
            int kq = idx & 7;
            int gr = row0 + r;
            float4 v = make_float4(0.f, 0.f, 0.f, 0.f);
            if (gr < N)
                v = *(const float4*)(X + (long long)gr * K + kt + kq * 4);
            if (RELU_IN) {
                int kb = kt + kq * 4;
                v.x = fmaxf(v.x + bs[kb + 0], 0.f);
                v.y = fmaxf(v.y + bs[kb + 1], 0.f);
                v.z = fmaxf(v.z + bs[kb + 2], 0.f);
                v.w = fmaxf(v.w + bs[kb + 3], 0.f);
            }
            float* p = Xs + r * XS + kq * 8;
            *(float2*)(p + 0) = make_float2(v.x, v.x);
            *(float2*)(p + 2) = make_float2(v.y, v.y);
            *(float2*)(p + 4) = make_float2(v.z, v.z);
            *(float2*)(p + 6) = make_float2(v.w, v.w);
        }
        __syncthreads();

        const float* Xr = Xs + (rg * 8) * XS;
        #pragma unroll
        for (int kk = 0; kk < KT / 2; kk++) {
            unsigned long long w0xy = *(const unsigned long long*)(Ws + (2 * kk) * 64 + cg * 4);
            unsigned long long w0zw = *(const unsigned long long*)(Ws + (2 * kk) * 64 + cg * 4 + 2);
            unsigned long long w1xy = *(const unsigned long long*)(Ws + (2 * kk + 1) * 64 + cg * 4);
            unsigned long long w1zw = *(const unsigned long long*)(Ws + (2 * kk + 1) * 64 + cg * 4 + 2);
            #pragma unroll
            for (int j = 0; j < 8; j++) {
                ulonglong2 xd = *(const ulonglong2*)(Xr + j * XS + kk * 4);
                ffma2(axy[j], xd.x, w0xy);
                ffma2(azw[j], xd.x, w0zw);
                ffma2(axy[j], xd.y, w1xy);
                ffma2(azw[j], xd.y, w1zw);
            }
        }
    }

    #pragma unroll
    for (int j = 0; j < 8; j++) {
        int gr = row0 + rg * 8 + j;
        if (gr < N) {
            float2 lo = *(float2*)&axy[j];
            float2 hi = *(float2*)&azw[j];
            __nv_bfloat162 b0 = __float22bfloat162_rn(lo);
            __nv_bfloat162 b1 = __float22bfloat162_rn(hi);
            uint2 pk;
            pk.x = *(unsigned*)&b0;
            pk.y = *(unsigned*)&b1;
            out[(long long)gr * 16 + cg] = pk;
        }
    }
}

// ---------------------------------------------------------------------------
// Aggregate from bf16 h: out[n] = sum over CSR bucket of h[src]*norm.
// Warp per node; 4 groups of 8 lanes, each group one record, lane gl owns
// 16B (8 bf16 features). fp32 accumulate, shfl-combine groups, unroll 4.
// EPI==1: fuse +b2 and log_softmax, write final output.
// ---------------------------------------------------------------------------
template <int EPI>
__global__ void k_agg(const uint4* __restrict__ h, float* __restrict__ out,
                      const float* __restrict__ bias, int N) {
    int node = blockIdx.x * 8 + (threadIdx.x >> 5);
    if (node >= N) return;
    int lane = threadIdx.x & 31;
    int grp = lane >> 3;     // record slot 0..3
    int gl  = lane & 7;      // 16B chunk within row
    int beg = g_off[node];
    int end = g_off[node + 1];

    float2 acc[4];
    #pragma unroll
    for (int i = 0; i < 4; i++) acc[i] = make_float2(0.f, 0.f);

    #pragma unroll 4
    for (int j = beg + grp; j < end; j += 4) {
        float2 r = g_rec[j];
        int s = __float_as_int(r.x);
        uint4 v = __ldg(h + (long long)s * 8 + gl);
        float2 f;
        f = __bfloat1622float2(*(__nv_bfloat162*)&v.x);
        acc[0].x += f.x * r.y; acc[0].y += f.y * r.y;
        f = __bfloat1622float2(*(__nv_bfloat162*)&v.y);
        acc[1].x += f.x * r.y; acc[1].y += f.y * r.y;
        f = __bfloat1622float2(*(__nv_bfloat162*)&v.z);
        acc[2].x += f.x * r.y; acc[2].y += f.y * r.y;
        f = __bfloat1622float2(*(__nv_bfloat162*)&v.w);
        acc[3].x += f.x * r.y; acc[3].y += f.y * r.y;
    }
    // combine the 4 record-groups (lanes with equal gl)
    #pragma unroll
    for (int i = 0; i < 4; i++) {
        acc[i].x += __shfl_xor_sync(0xffffffffu, acc[i].x, 8);
        acc[i].y += __shfl_xor_sync(0xffffffffu, acc[i].y, 8);
        acc[i].x += __shfl_xor_sync(0xffffffffu, acc[i].x, 16);
        acc[i].y += __shfl_xor_sync(0xffffffffu, acc[i].y, 16);
    }

    if (EPI == 0) {
        if (lane < 8) {
            float4* op = (float4*)(out + (long long)node * 64 + gl * 8);
            op[0] = make_float4(acc[0].x, acc[0].y, acc[1].x, acc[1].y);
            op[1] = make_float4(acc[2].x, acc[2].y, acc[3].x, acc[3].y);
        }
    } else {
        const float4* bp = (const float4*)(bias + gl * 8);
        float4 b0 = bp[0], b1 = bp[1];
        acc[0].x += b0.x; acc[0].y += b0.y; acc[1].x += b0.z; acc[1].y += b0.w;
        acc[2].x += b1.x; acc[2].y += b1.y; acc[3].x += b1.z; acc[3].y += b1.w;
        float m = fmaxf(fmaxf(fmaxf(acc[0].x, acc[0].y), fmaxf(acc[1].x, acc[1].y)),
                        fmaxf(fmaxf(acc[2].x, acc[2].y), fmaxf(acc[3].x, acc[3].y)));
        #pragma unroll
        for (int o = 1; o < 8; o <<= 1)
            m = fmaxf(m, __shfl_xor_sync(0xffffffffu, m, o));
        float s = expf(acc[0].x - m) + expf(acc[0].y - m)
                + expf(acc[1].x - m) + expf(acc[1].y - m)
                + expf(acc[2].x - m) + expf(acc[2].y - m)
                + expf(acc[3].x - m) + expf(acc[3].y - m);
        #pragma unroll
        for (int o = 1; o < 8; o <<= 1)
            s += __shfl_xor_sync(0xffffffffu, s, o);
        float lse = m + logf(s);
        if (lane < 8) {
            float4* op = (float4*)(out + (long long)node * 64 + gl * 8);
            op[0] = make_float4(acc[0].x - lse, acc[0].y - lse,
                                acc[1].x - lse, acc[1].y - lse);
            op[1] = make_float4(acc[2].x - lse, acc[2].y - lse,
                                acc[3].x - lse, acc[3].y - lse);
        }
    }
}

// ---------------------------------------------------------------------------
extern "C" void kernel_launch(void* const* d_in, const int* in_sizes, int n_in,
                              void* d_out, int out_size) {
    const float* x  = (const float*)d_in[0];
    const void*  ei = d_in[1];
    const float* W1 = (const float*)d_in[2];
    const float* b1 = (const float*)d_in[3];
    const float* W2 = (const float*)d_in[4];
    const float* b2 = (const float*)d_in[5];
    float* out = (float*)d_out;

    int N = in_sizes[0] / 128;                 // 100000
    long long E = (long long)in_sizes[1] / 2;  // 1600000

    static cudaStream_t s2 = nullptr;
    static cudaEvent_t evFork = nullptr, evJoin = nullptr;
    if (!s2) {
        cudaStreamCreateWithFlags(&s2, cudaStreamNonBlocking);
        cudaEventCreateWithFlags(&evFork, cudaEventDisableTiming);
        cudaEventCreateWithFlags(&evJoin, cudaEventDisableTiming);
    }

    uint4* ph;
    float* pagg;
    cudaGetSymbolAddress((void**)&ph, g_h);
    cudaGetSymbolAddress((void**)&pagg, g_agg);

    int nb    = (N + 255) / 256;   // 391 blocks: one wave, grid-barrier safe
    int bGemm = (N + 127) / 128;
    int bAgg  = (N + 7) / 8;

    // Fork: GEMM1 (x,W1 only) on s2, concurrent with one-kernel CSR prep.
    cudaEventRecord(evFork, 0);
    cudaStreamWaitEvent(s2, evFork, 0);
    k_gemm<128, 0><<<bGemm, 256, 0, s2>>>(x, W1, nullptr, (uint2*)ph, N);
    cudaEventRecord(evJoin, s2);

    k_prep<<<nb, 256>>>(ei, E, N, nb);

    // Join: aggregation needs both g_h (s2) and g_rec/g_off (default)
    cudaStreamWaitEvent(0, evJoin, 0);

    // layer 1 aggregate (fp32 out)
    k_agg<0><<<bAgg, 256>>>(ph, pagg, nullptr, N);

    // layer 2: h2 = relu(agg1 + b1) @ W2 (bf16, overwrites g_h — safe: agg0 done)
    k_gemm<64, 1><<<bGemm, 256>>>(pagg, W2, b1, (uint2*)ph, N);

    // final aggregate + b2 + log_softmax
    k_agg<1><<<bAgg, 256>>>(ph, out, b2, N);
}

// round 9
// speedup vs baseline: 1.1240x; 1.1143x over previous
#include <cuda_runtime.h>
#include <cuda_bf16.h>
#include <math.h>

// Fixed problem shape (from setup_inputs): N=100000, E=1600000, F_IN=128, H=C=64
#define NNODES 100000
#define HD 64
#define MSGMAX 1800000   // E + N with headroom

// Scratch (allocation-free: __device__ globals)
__device__ int       g_cnt[NNODES];         // per-dst message count (incl. self-loop)
__device__ int       g_off[NNODES + 1];     // CSR offsets
__device__ int       g_cur[NNODES];         // placement cursors
__device__ long long g_desc[512];           // lookback descriptors {flag,val}
__device__ float2    g_rec[MSGMAX];         // per-message {src_bits, norm}
__device__ uint4     g_h[NNODES * 8];       // bf16 h (layer1), then bf16 h2 (layer2 out)
__device__ uint4     g_hb[NNODES * 8];      // bf16 relu(agg1+b1) = GEMM2 input
__device__ int       g_is64;                // edge_index dtype flag

__device__ __forceinline__ long long load_edge(const void* ei, long long pos) {
    if (g_is64) return ((const long long*)ei)[pos];
    return (long long)((const int*)ei)[pos];
}

__device__ __forceinline__ void ffma2(unsigned long long& d, unsigned long long a,
                                      unsigned long long b) {
    asm("fma.rn.f32x2 %0, %1, %2, %0;" : "+l"(d) : "l"(a), "l"(b));
}

// ---------------------------------------------------------------------------
// init: cnt = 1 (self loop), zero lookback descriptors, detect index width
// ---------------------------------------------------------------------------
__global__ void k_init(const void* ei, int N) {
    int i = blockIdx.x * 256 + threadIdx.x;
    if (i < N) g_cnt[i] = 1;
    if (i < 512) g_desc[i] = 0;
    if (i == 0) {
        const unsigned long long* p = (const unsigned long long*)ei;
        int ok = 1;
        #pragma unroll 4
        for (int j = 0; j < 64; j++)
            if (p[j] >= (unsigned long long)N) ok = 0;
        g_is64 = ok;
    }
}

// ---------------------------------------------------------------------------
// degree count over dst
// ---------------------------------------------------------------------------
__global__ void k_count(const void* ei, long long E) {
    long long e = (long long)blockIdx.x * 256 + threadIdx.x;
    if (e < E) {
        int d = (int)load_edge(ei, E + e);
        atomicAdd(&g_cnt[d], 1);
    }
}

// ---------------------------------------------------------------------------
// Single-pass exclusive scan via decoupled lookback (waits only on LOWER
// block ids, which are dispatched earlier => deadlock-free even co-resident
// with GEMM1). Packed 64-bit {flag<<32 | value}; flag: 1=agg, 2=prefix.
// ---------------------------------------------------------------------------
__global__ void k_scan(int N) {
    __shared__ int s[256];
    __shared__ int sbase;
    int b = blockIdx.x, tid = threadIdx.x;
    int i = b * 256 + tid;
    int v = (i < N) ? g_cnt[i] : 0;
    s[tid] = v;
    __syncthreads();
    #pragma unroll
    for (int o = 1; o < 256; o <<= 1) {
        int tv = (tid >= o) ? s[tid - o] : 0;
        __syncthreads();
        s[tid] += tv;
        __syncthreads();
    }
    int incl = s[tid];
    int bsum = s[255];

    volatile long long* desc = (volatile long long*)g_desc;
    if (tid == 0) {
        if (b == 0) { desc[0] = (2LL << 32) | (unsigned)bsum; sbase = 0; }
        else        { desc[b] = (1LL << 32) | (unsigned)bsum; }
    }
    if (b > 0 && tid < 32) {
        int lane = tid;
        int base = 0;
        int j = b - 1;
        while (true) {
            int idx = j - lane;
            int f = 0, val = 0;
            if (idx >= 0) {
                long long dsc;
                do { dsc = desc[idx]; } while ((int)(dsc >> 32) == 0);
                f = (int)(dsc >> 32);
                val = (int)(unsigned)dsc;
            }
            unsigned pm = __ballot_sync(0xffffffffu, f == 2);
            if (pm) {
                int firstLane = __ffs(pm) - 1;
                int contrib = (lane <= firstLane) ? val : 0;
                #pragma unroll
                for (int o = 16; o > 0; o >>= 1)
                    contrib += __shfl_xor_sync(0xffffffffu, contrib, o);
                base += contrib;
                break;
            } else {
                int contrib = val;
                #pragma unroll
                for (int o = 16; o > 0; o >>= 1)
                    contrib += __shfl_xor_sync(0xffffffffu, contrib, o);
                base += contrib;
                j -= 32;
            }
        }
        if (lane == 0) {
            desc[b] = (2LL << 32) | (unsigned)(base + bsum);
            sbase = base;
        }
    }
    __syncthreads();
    int base = sbase;
    if (i < N) {
        int off = base + incl - v;
        g_off[i] = off;
        g_cur[i] = off;
        if (i == N - 1) g_off[N] = off + v;
    }
}

// ---------------------------------------------------------------------------
// place: bucket message records {src, rsqrt(deg_s*deg_d)} by dst
// ---------------------------------------------------------------------------
__global__ void k_place(const void* ei, long long E, int N) {
    long long e = (long long)blockIdx.x * 256 + threadIdx.x;
    long long M = E + (long long)N;
    if (e >= M) return;
    int s, d;
    if (e < E) {
        s = (int)load_edge(ei, e);
        d = (int)load_edge(ei, E + e);
    } else {
        s = d = (int)(e - E);
    }
    float nrm = rsqrtf((float)(g_cnt[s] * g_cnt[d]));
    int pos = atomicAdd(&g_cur[d], 1);
    g_rec[pos] = make_float2(__int_as_float(s), nrm);
}

// ---------------------------------------------------------------------------
// GEMM1: out[N,64](bf16) = X[N,128] @ W[128,64].  FFMA2 core (proven R5).
// ---------------------------------------------------------------------------
template <int K>
__global__ __launch_bounds__(256, 2)
void k_gemm(const float* __restrict__ X, const float* __restrict__ W,
            uint2* __restrict__ out, int N) {
    const int KT = 32;
    const int XS = 68;
    __shared__ float Ws[KT * 64];
    __shared__ float Xs[128 * XS];

    int tid = threadIdx.x;
    int cg = tid & 15;
    int rg = tid >> 4;
    int row0 = blockIdx.x * 128;

    unsigned long long axy[8], azw[8];
    #pragma unroll
    for (int j = 0; j < 8; j++) { axy[j] = 0ull; azw[j] = 0ull; }

    for (int kt = 0; kt < K; kt += KT) {
        __syncthreads();
        {
            const float4* Wg = (const float4*)W + (long long)kt * 16;
            float4* Wt = (float4*)Ws;
            Wt[tid]       = Wg[tid];
            Wt[tid + 256] = Wg[tid + 256];
        }
        #pragma unroll
        for (int i = 0; i < 4; i++) {
            int idx = i * 256 + tid;
            int r  = idx >> 3;
            int kq = idx & 7;
            int gr = row0 + r;
            float4 v = make_float4(0.f, 0.f, 0.f, 0.f);
            if (gr < N)
                v = *(const float4*)(X + (long long)gr * K + kt + kq * 4);
            float* p = Xs + r * XS + kq * 8;
            *(float2*)(p + 0) = make_float2(v.x, v.x);
            *(float2*)(p + 2) = make_float2(v.y, v.y);
            *(float2*)(p + 4) = make_float2(v.z, v.z);
            *(float2*)(p + 6) = make_float2(v.w, v.w);
        }
        __syncthreads();

        const float* Xr = Xs + (rg * 8) * XS;
        #pragma unroll
        for (int kk = 0; kk < KT / 2; kk++) {
            unsigned long long w0xy = *(const unsigned long long*)(Ws + (2 * kk) * 64 + cg * 4);
            unsigned long long w0zw = *(const unsigned long long*)(Ws + (2 * kk) * 64 + cg * 4 + 2);
            unsigned long long w1xy = *(const unsigned long long*)(Ws + (2 * kk + 1) * 64 + cg * 4);
            unsigned long long w1zw = *(const unsigned long long*)(Ws + (2 * kk + 1) * 64 + cg * 4 + 2);
            #pragma unroll
            for (int j = 0; j < 8; j++) {
                ulonglong2 xd = *(const ulonglong2*)(Xr + j * XS + kk * 4);
                ffma2(axy[j], xd.x, w0xy);
                ffma2(azw[j], xd.x, w0zw);
                ffma2(axy[j], xd.y, w1xy);
                ffma2(azw[j], xd.y, w1zw);
            }
        }
    }

    #pragma unroll
    for (int j = 0; j < 8; j++) {
        int gr = row0 + rg * 8 + j;
        if (gr < N) {
            float2 lo = *(float2*)&axy[j];
            float2 hi = *(float2*)&azw[j];
            __nv_bfloat162 b0 = __float22bfloat162_rn(lo);
            __nv_bfloat162 b1 = __float22bfloat162_rn(hi);
            uint2 pk;
            pk.x = *(unsigned*)&b0;
            pk.y = *(unsigned*)&b1;
            out[(long long)gr * 16 + cg] = pk;
        }
    }
}

// ---------------------------------------------------------------------------
// GEMM2: out[N,64](bf16) = Xb[N,64](bf16) @ W[64,64].
// 64-row tiles, 4x4 thread tile, plain FMA, low smem/regs => 3-4 CTAs/SM
// (GEMM2 is latency-bound per R8 ncu: occ 22.8%, issue 34.7%).
// ---------------------------------------------------------------------------
__global__ __launch_bounds__(256)
void k_gemm2(const uint2* __restrict__ Xb, const float* __restrict__ W,
             uint2* __restrict__ out, int N) {
    const int XS = 68;
    __shared__ float Xs[64 * XS];       // 17.4 KB (fp32, converted from bf16)
    __shared__ float Ws[32 * 64];       // 8 KB

    int tid = threadIdx.x;
    int cg = tid & 15;
    int rg = tid >> 4;                   // 16 row-groups x 4 rows
    int row0 = blockIdx.x * 64;

    // load X tile [64 rows][64 bf16] -> fp32 smem; 1024 uint2, 4 per thread
    #pragma unroll
    for (int i = 0; i < 4; i++) {
        int idx = i * 256 + tid;
        int r = idx >> 4;
        int c = idx & 15;
        int gr = row0 + r;
        float2 f0 = make_float2(0.f, 0.f), f1 = make_float2(0.f, 0.f);
        if (gr < N) {
            uint2 v = __ldg(Xb + (long long)gr * 16 + c);
            f0 = __bfloat1622float2(*(__nv_bfloat162*)&v.x);
            f1 = __bfloat1622float2(*(__nv_bfloat162*)&v.y);
        }
        *(float4*)(Xs + r * XS + c * 4) = make_float4(f0.x, f0.y, f1.x, f1.y);
    }

    float4 acc[4];
    #pragma unroll
    for (int j = 0; j < 4; j++) acc[j] = make_float4(0.f, 0.f, 0.f, 0.f);

    #pragma unroll
    for (int kt = 0; kt < 64; kt += 32) {
        __syncthreads();                 // protects Xs (first iter) + Ws reuse
        {
            const float4* Wg = (const float4*)W + (long long)kt * 16;
            float4* Wt = (float4*)Ws;
            Wt[tid]       = Wg[tid];
            Wt[tid + 256] = Wg[tid + 256];
        }
        __syncthreads();
        const float4* Ws4 = (const float4*)Ws;
        #pragma unroll
        for (int k4 = 0; k4 < 8; k4++) {
            float4 w0 = Ws4[(k4 * 4 + 0) * 16 + cg];
            float4 w1 = Ws4[(k4 * 4 + 1) * 16 + cg];
            float4 w2 = Ws4[(k4 * 4 + 2) * 16 + cg];
            float4 w3 = Ws4[(k4 * 4 + 3) * 16 + cg];
            #pragma unroll
            for (int j = 0; j < 4; j++) {
                float4 xv = *(const float4*)(Xs + (rg * 4 + j) * XS + kt + k4 * 4);
                acc[j].x += xv.x * w0.x + xv.y * w1.x + xv.z * w2.x + xv.w * w3.x;
                acc[j].y += xv.x * w0.y + xv.y * w1.y + xv.z * w2.y + xv.w * w3.y;
                acc[j].z += xv.x * w0.z + xv.y * w1.z + xv.z * w2.z + xv.w * w3.z;
                acc[j].w += xv.x * w0.w + xv.y * w1.w + xv.z * w2.w + xv.w * w3.w;
            }
        }
    }

    #pragma unroll
    for (int j = 0; j < 4; j++) {
        int gr = row0 + rg * 4 + j;
        if (gr < N) {
            __nv_bfloat162 b0 = __float22bfloat162_rn(make_float2(acc[j].x, acc[j].y));
            __nv_bfloat162 b1 = __float22bfloat162_rn(make_float2(acc[j].z, acc[j].w));
            uint2 pk;
            pk.x = *(unsigned*)&b0;
            pk.y = *(unsigned*)&b1;
            out[(long long)gr * 16 + cg] = pk;
        }
    }
}

// ---------------------------------------------------------------------------
// Aggregate from bf16 h: sum over CSR bucket of h[src]*norm.  Warp per node;
// 4 groups of 8 lanes, lane gl owns 16B (8 bf16). fp32 accumulate.
// EPI==0: +b1, relu, write bf16 (GEMM2 input).
// EPI==1: +b2, log_softmax, write fp32 output.
// ---------------------------------------------------------------------------
template <int EPI>
__global__ void k_agg(const uint4* __restrict__ h, void* __restrict__ outp,
                      const float* __restrict__ bias, int N) {
    int node = blockIdx.x * 8 + (threadIdx.x >> 5);
    if (node >= N) return;
    int lane = threadIdx.x & 31;
    int grp = lane >> 3;
    int gl  = lane & 7;
    int beg = g_off[node];
    int end = g_off[node + 1];

    float2 acc[4];
    #pragma unroll
    for (int i = 0; i < 4; i++) acc[i] = make_float2(0.f, 0.f);

    #pragma unroll 4
    for (int j = beg + grp; j < end; j += 4) {
        float2 r = g_rec[j];
        int s = __float_as_int(r.x);
        uint4 v = __ldg(h + (long long)s * 8 + gl);
        float2 f;
        f = __bfloat1622float2(*(__nv_bfloat162*)&v.x);
        acc[0].x += f.x * r.y; acc[0].y += f.y * r.y;
        f = __bfloat1622float2(*(__nv_bfloat162*)&v.y);
        acc[1].x += f.x * r.y; acc[1].y += f.y * r.y;
        f = __bfloat1622float2(*(__nv_bfloat162*)&v.z);
        acc[2].x += f.x * r.y; acc[2].y += f.y * r.y;
        f = __bfloat1622float2(*(__nv_bfloat162*)&v.w);
        acc[3].x += f.x * r.y; acc[3].y += f.y * r.y;
    }
    #pragma unroll
    for (int i = 0; i < 4; i++) {
        acc[i].x += __shfl_xor_sync(0xffffffffu, acc[i].x, 8);
        acc[i].y += __shfl_xor_sync(0xffffffffu, acc[i].y, 8);
        acc[i].x += __shfl_xor_sync(0xffffffffu, acc[i].x, 16);
        acc[i].y += __shfl_xor_sync(0xffffffffu, acc[i].y, 16);
    }

    const float4* bp = (const float4*)(bias + gl * 8);
    float4 b0 = bp[0], b1 = bp[1];
    acc[0].x += b0.x; acc[0].y += b0.y; acc[1].x += b0.z; acc[1].y += b0.w;
    acc[2].x += b1.x; acc[2].y += b1.y; acc[3].x += b1.z; acc[3].y += b1.w;

    if (EPI == 0) {
        if (lane < 8) {
            #pragma unroll
            for (int i = 0; i < 4; i++) {
                acc[i].x = fmaxf(acc[i].x, 0.f);
                acc[i].y = fmaxf(acc[i].y, 0.f);
            }
            __nv_bfloat162 p0 = __float22bfloat162_rn(acc[0]);
            __nv_bfloat162 p1 = __float22bfloat162_rn(acc[1]);
            __nv_bfloat162 p2 = __float22bfloat162_rn(acc[2]);
            __nv_bfloat162 p3 = __float22bfloat162_rn(acc[3]);
            uint4 pk;
            pk.x = *(unsigned*)&p0; pk.y = *(unsigned*)&p1;
            pk.z = *(unsigned*)&p2; pk.w = *(unsigned*)&p3;
            ((uint4*)outp)[(long long)node * 8 + gl] = pk;
        }
    } else {
        float m = fmaxf(fmaxf(fmaxf(acc[0].x, acc[0].y), fmaxf(acc[1].x, acc[1].y)),
                        fmaxf(fmaxf(acc[2].x, acc[2].y), fmaxf(acc[3].x, acc[3].y)));
        #pragma unroll
        for (int o = 1; o < 8; o <<= 1)
            m = fmaxf(m, __shfl_xor_sync(0xffffffffu, m, o));
        float s = expf(acc[0].x - m) + expf(acc[0].y - m)
                + expf(acc[1].x - m) + expf(acc[1].y - m)
                + expf(acc[2].x - m) + expf(acc[2].y - m)
                + expf(acc[3].x - m) + expf(acc[3].y - m);
        #pragma unroll
        for (int o = 1; o < 8; o <<= 1)
            s += __shfl_xor_sync(0xffffffffu, s, o);
        float lse = m + logf(s);
        if (lane < 8) {
            float* out = (float*)outp;
            float4* op = (float4*)(out + (long long)node * 64 + gl * 8);
            op[0] = make_float4(acc[0].x - lse, acc[0].y - lse,
                                acc[1].x - lse, acc[1].y - lse);
            op[1] = make_float4(acc[2].x - lse, acc[2].y - lse,
                                acc[3].x - lse, acc[3].y - lse);
        }
    }
}

// ---------------------------------------------------------------------------
extern "C" void kernel_launch(void* const* d_in, const int* in_sizes, int n_in,
                              void* d_out, int out_size) {
    const float* x  = (const float*)d_in[0];
    const void*  ei = d_in[1];
    const float* W1 = (const float*)d_in[2];
    const float* b1 = (const float*)d_in[3];
    const float* W2 = (const float*)d_in[4];
    const float* b2 = (const float*)d_in[5];
    float* out = (float*)d_out;

    int N = in_sizes[0] / 128;                 // 100000
    long long E = (long long)in_sizes[1] / 2;  // 1600000
    long long M = E + (long long)N;

    static cudaStream_t s2 = nullptr;
    static cudaEvent_t evFork = nullptr, evJoin = nullptr;
    if (!s2) {
        cudaStreamCreateWithFlags(&s2, cudaStreamNonBlocking);
        cudaEventCreateWithFlags(&evFork, cudaEventDisableTiming);
        cudaEventCreateWithFlags(&evJoin, cudaEventDisableTiming);
    }

    uint4 *ph, *phb;
    cudaGetSymbolAddress((void**)&ph, g_h);
    cudaGetSymbolAddress((void**)&phb, g_hb);

    int bN     = (N + 255) / 256;
    int bDeg   = (int)((E + 255) / 256);
    int bMsg   = (int)((M + 255) / 256);
    int bGemm1 = (N + 127) / 128;
    int bGemm2 = (N + 63) / 64;
    int bAgg   = (N + 7) / 8;

    // Fork: GEMM1 (x,W1 only) on s2, concurrent with CSR prep on capture stream.
    cudaEventRecord(evFork, 0);
    cudaStreamWaitEvent(s2, evFork, 0);
    k_gemm<128><<<bGemm1, 256, 0, s2>>>(x, W1, (uint2*)ph, N);
    cudaEventRecord(evJoin, s2);

    k_init<<<bN, 256>>>(ei, N);
    k_count<<<bDeg, 256>>>(ei, E);
    k_scan<<<bN, 256>>>(N);
    k_place<<<bMsg, 256>>>(ei, E, N);

    // Join: aggregation needs both g_h (s2) and g_rec/g_off (default)
    cudaStreamWaitEvent(0, evJoin, 0);

    // layer-1 aggregate + b1 + relu -> bf16 g_hb
    k_agg<0><<<bAgg, 256>>>(ph, phb, b1, N);

    // layer 2 GEMM: bf16 in (g_hb) -> bf16 out (g_h; safe, agg0 done with it)
    k_gemm2<<<bGemm2, 256>>>((const uint2*)phb, W2, (uint2*)ph, N);

    // final aggregate + b2 + log_softmax
    k_agg<1><<<bAgg, 256>>>(ph, out, b2, N);
}

// round 11
// speedup vs baseline: 1.3365x; 1.1891x over previous
#include <cuda_runtime.h>
#include <cuda_bf16.h>
#include <math.h>
#include <stdint.h>

// Fixed problem shape (from setup_inputs): N=100000, E=1600000, F_IN=128, H=C=64
#define NNODES 100000
#define HD 64
#define MSGMAX 1800000   // E + N with headroom

// Scratch (allocation-free: __device__ globals)
__device__ int    g_cnt[NNODES];            // per-dst message count (incl. self-loop)
__device__ int    g_off[NNODES + 1];        // CSR offsets
__device__ int    g_cur[NNODES];            // placement cursors
__device__ int    g_bsum[512];              // block sums for scan
__device__ int    g_boff[512];              // block offsets for scan
__device__ float2 g_rec[MSGMAX];            // per-message {src_bits, norm}
__device__ uint4  g_h[NNODES * 8];          // GEMM output in bf16 (64 bf16 = 8 uint4/row)
__device__ float  g_agg[NNODES * HD];       // layer-1 aggregate (fp32)
__device__ int    g_is64;                   // edge_index dtype flag

__device__ __forceinline__ long long load_edge(const void* ei, long long pos) {
    if (g_is64) return ((const long long*)ei)[pos];
    return (long long)((const int*)ei)[pos];
}

__device__ __forceinline__ void ffma2(unsigned long long& d, unsigned long long a,
                                      unsigned long long b) {
    asm("fma.rn.f32x2 %0, %1, %2, %0;" : "+l"(d) : "l"(a), "l"(b));
}

// ---------------------------------------------------------------------------
// init: cnt = 1 (self loop), detect index width
// ---------------------------------------------------------------------------
__global__ void k_init(const void* ei, int N) {
    int i = blockIdx.x * 256 + threadIdx.x;
    if (i < N) g_cnt[i] = 1;
    if (i == 0) {
        const unsigned long long* p = (const unsigned long long*)ei;
        int ok = 1;
        #pragma unroll 4
        for (int j = 0; j < 64; j++)
            if (p[j] >= (unsigned long long)N) ok = 0;
        g_is64 = ok;
    }
}

// ---------------------------------------------------------------------------
// degree count over dst
// ---------------------------------------------------------------------------
__global__ void k_count(const void* ei, long long E) {
    long long e = (long long)blockIdx.x * 256 + threadIdx.x;
    if (e < E) {
        int d = (int)load_edge(ei, E + e);
        atomicAdd(&g_cnt[d], 1);
    }
}

// ---------------------------------------------------------------------------
// 3-phase exclusive scan of g_cnt -> g_off  (R5-proven)
// ---------------------------------------------------------------------------
__global__ void k_scan1(int N) {
    __shared__ int s[256];
    int i = blockIdx.x * 256 + threadIdx.x;
    int v = (i < N) ? g_cnt[i] : 0;
    s[threadIdx.x] = v;
    __syncthreads();
    #pragma unroll
    for (int o = 128; o > 0; o >>= 1) {
        if (threadIdx.x < o) s[threadIdx.x] += s[threadIdx.x + o];
        __syncthreads();
    }
    if (threadIdx.x == 0) g_bsum[blockIdx.x] = s[0];
}

__global__ void k_scan2(int nb) {
    __shared__ int wsum[16];
    int t = threadIdx.x;
    int lane = t & 31;
    int w = t >> 5;
    int v = (t < nb) ? g_bsum[t] : 0;
    int x = v;
    #pragma unroll
    for (int o = 1; o < 32; o <<= 1) {
        int y = __shfl_up_sync(0xffffffffu, x, o);
        if (lane >= o) x += y;
    }
    if (lane == 31) wsum[w] = x;
    __syncthreads();
    if (w == 0) {
        int ws = (lane < 16) ? wsum[lane] : 0;
        #pragma unroll
        for (int o = 1; o < 16; o <<= 1) {
            int y = __shfl_up_sync(0xffffffffu, ws, o);
            if (lane >= o) ws += y;
        }
        if (lane < 16) wsum[lane] = ws;
    }
    __syncthreads();
    int base = (w > 0) ? wsum[w - 1] : 0;
    if (t < nb) g_boff[t] = base + x - v;
}

__global__ void k_scan3(int N) {
    __shared__ int s[256];
    int i = blockIdx.x * 256 + threadIdx.x;
    int v = (i < N) ? g_cnt[i] : 0;
    s[threadIdx.x] = v;
    __syncthreads();
    #pragma unroll
    for (int o = 1; o < 256; o <<= 1) {
        int tv = (threadIdx.x >= o) ? s[threadIdx.x - o] : 0;
        __syncthreads();
        s[threadIdx.x] += tv;
        __syncthreads();
    }
    if (i < N) {
        int off = g_boff[blockIdx.x] + s[threadIdx.x] - v;
        g_off[i] = off;
        g_cur[i] = off;
        if (i == N - 1) g_off[N] = off + v;
    }
}

// ---------------------------------------------------------------------------
// place: bucket message records {src, rsqrt(deg_s*deg_d)} by dst
// ---------------------------------------------------------------------------
__global__ void k_place(const void* ei, long long E, int N) {
    long long e = (long long)blockIdx.x * 256 + threadIdx.x;
    long long M = E + (long long)N;
    if (e >= M) return;
    int s, d;
    if (e < E) {
        s = (int)load_edge(ei, e);
        d = (int)load_edge(ei, E + e);
    } else {
        s = d = (int)(e - E);
    }
    float nrm = rsqrtf((float)(g_cnt[s] * g_cnt[d]));
    int pos = atomicAdd(&g_cur[d], 1);
    g_rec[pos] = make_float2(__int_as_float(s), nrm);
}

// ---------------------------------------------------------------------------
// GEMM1 via mma.sync bf16 HMMA (sm_80+ baseline feature; tcgen05 needs the
// 'a' target which this toolchain doesn't emit).
// CTA: 128 rows x 64 cols x K=128. 8 warps, warp tile m16 x n64.
// X: fp32 -> bf16 smem, row stride 136 bf16 (A-frag loads conflict-free:
//    bank = 4*groupID + tig, all 32 distinct).
// W: pre-packed into fragment layout Wf[ks][nt][lane] = {b0b1, b2b3} so one
//    LDS.64 feeds each B fragment.
// D: fp32 accum in regs -> bf16 g_h.
// ---------------------------------------------------------------------------
#define G1_XSTRIDE 136                    // bf16 units per X smem row
#define G1_XS_BYTES (128 * G1_XSTRIDE * 2)   // 34816
#define G1_WF_OFF   G1_XS_BYTES
#define G1_SMEM_TOT (G1_XS_BYTES + 8 * 8 * 32 * 8)   // + 16384 = 51200

__global__ __launch_bounds__(256)
void k_gemm1_mma(const float* __restrict__ X, const float* __restrict__ W,
                 unsigned* __restrict__ out, int N) {
    extern __shared__ char smem[];
    __nv_bfloat16* Xs = (__nv_bfloat16*)smem;
    uint2* Wf = (uint2*)(smem + G1_WF_OFF);

    int tid = threadIdx.x;
    int wid = tid >> 5, lane = tid & 31;
    int tig = lane & 3, gid = lane >> 2;
    int row0 = blockIdx.x * 128;

    // Pack W fragments: Wf[(ks*8+nt)*32 + lane] = {bf16x2(b0,b1), bf16x2(b2,b3)}
    for (int idx = tid; idx < 2048; idx += 256) {
        int l = idx & 31;
        int nt = (idx >> 5) & 7;
        int ks = idx >> 8;
        int lt = l & 3, lg = l >> 2;
        int k0 = ks * 16 + lt * 2;
        int n  = nt * 8 + lg;
        float b0 = W[(long long)k0 * 64 + n];
        float b1 = W[(long long)(k0 + 1) * 64 + n];
        float b2 = W[(long long)(k0 + 8) * 64 + n];
        float b3 = W[(long long)(k0 + 9) * 64 + n];
        __nv_bfloat162 p0 = __float22bfloat162_rn(make_float2(b0, b1));
        __nv_bfloat162 p1 = __float22bfloat162_rn(make_float2(b2, b3));
        Wf[idx] = make_uint2(*(unsigned*)&p0, *(unsigned*)&p1);
    }

    // X tile fp32 -> bf16 smem (coalesced float4 reads)
    for (int idx = tid; idx < 128 * 32; idx += 256) {
        int r  = idx >> 5;
        int c4 = idx & 31;          // float4 index: col = c4*4
        int gr = row0 + r;
        float4 v = make_float4(0.f, 0.f, 0.f, 0.f);
        if (gr < N) v = *(const float4*)(X + (long long)gr * 128 + c4 * 4);
        __nv_bfloat162 p0 = __float22bfloat162_rn(make_float2(v.x, v.y));
        __nv_bfloat162 p1 = __float22bfloat162_rn(make_float2(v.z, v.w));
        *(uint2*)((char*)Xs + ((long long)r * G1_XSTRIDE + c4 * 4) * 2) =
            make_uint2(*(unsigned*)&p0, *(unsigned*)&p1);
    }
    __syncthreads();

    float acc[8][4];
    #pragma unroll
    for (int nt = 0; nt < 8; nt++)
        #pragma unroll
        for (int q = 0; q < 4; q++) acc[nt][q] = 0.f;

    int rw = wid * 16;              // warp's row base within tile
    const char* XsB = (const char*)Xs;

    #pragma unroll
    for (int ks = 0; ks < 8; ks++) {
        int cbase = ks * 16 + tig * 2;
        unsigned A0 = *(const unsigned*)(XsB + ((rw + gid)     * G1_XSTRIDE + cbase)     * 2);
        unsigned A1 = *(const unsigned*)(XsB + ((rw + gid + 8) * G1_XSTRIDE + cbase)     * 2);
        unsigned A2 = *(const unsigned*)(XsB + ((rw + gid)     * G1_XSTRIDE + cbase + 8) * 2);
        unsigned A3 = *(const unsigned*)(XsB + ((rw + gid + 8) * G1_XSTRIDE + cbase + 8) * 2);
        #pragma unroll
        for (int nt = 0; nt < 8; nt++) {
            uint2 bb = Wf[(ks * 8 + nt) * 32 + lane];
            asm volatile(
                "mma.sync.aligned.m16n8k16.row.col.f32.bf16.bf16.f32 "
                "{%0,%1,%2,%3}, {%4,%5,%6,%7}, {%8,%9}, {%0,%1,%2,%3};"
                : "+f"(acc[nt][0]), "+f"(acc[nt][1]),
                  "+f"(acc[nt][2]), "+f"(acc[nt][3])
                : "r"(A0), "r"(A1), "r"(A2), "r"(A3),
                  "r"(bb.x), "r"(bb.y));
        }
    }

    // store D -> bf16 g_h (row = 32 unsigned words of bf16x2)
    int gr0 = row0 + rw + gid;
    int gr1 = gr0 + 8;
    #pragma unroll
    for (int nt = 0; nt < 8; nt++) {
        int cw = nt * 4 + tig;      // word index within row
        if (gr0 < N) {
            __nv_bfloat162 p = __float22bfloat162_rn(
                make_float2(acc[nt][0], acc[nt][1]));
            out[(long long)gr0 * 32 + cw] = *(unsigned*)&p;
        }
        if (gr1 < N) {
            __nv_bfloat162 p = __float22bfloat162_rn(
                make_float2(acc[nt][2], acc[nt][3]));
            out[(long long)gr1 * 32 + cw] = *(unsigned*)&p;
        }
    }
}

// ---------------------------------------------------------------------------
// GEMM2 (R5-proven): out[N,64](bf16) = relu(X[N,64]+b1) @ W2.  FFMA2 core.
// ---------------------------------------------------------------------------
template <int K, int RELU_IN>
__global__ __launch_bounds__(256, 2)
void k_gemm(const float* __restrict__ X, const float* __restrict__ W,
            const float* __restrict__ bias, uint2* __restrict__ out, int N) {
    const int KT = 32;
    const int XS = 68;
    __shared__ float Ws[KT * 64];
    __shared__ float Xs[128 * XS];
    __shared__ float bs[64];

    int tid = threadIdx.x;
    int cg = tid & 15;
    int rg = tid >> 4;
    int row0 = blockIdx.x * 128;

    if (RELU_IN && tid < 64) bs[tid] = bias[tid];

    unsigned long long axy[8], azw[8];
    #pragma unroll
    for (int j = 0; j < 8; j++) { axy[j] = 0ull; azw[j] = 0ull; }

    for (int kt = 0; kt < K; kt += KT) {
        __syncthreads();
        {
            const float4* Wg = (const float4*)W + (long long)kt * 16;
            float4* Wt = (float4*)Ws;
            Wt[tid]       = Wg[tid];
            Wt[tid + 256] = Wg[tid + 256];
        }
        #pragma unroll
        for (int i = 0; i < 4; i++) {
            int idx = i * 256 + tid;
            int r  = idx >> 3;
            int kq = idx & 7;
            int gr = row0 + r;
            float4 v = make_float4(0.f, 0.f, 0.f, 0.f);
            if (gr < N)
                v = *(const float4*)(X + (long long)gr * K + kt + kq * 4);
            if (RELU_IN) {
                int kb = kt + kq * 4;
                v.x = fmaxf(v.x + bs[kb + 0], 0.f);
                v.y = fmaxf(v.y + bs[kb + 1], 0.f);
                v.z = fmaxf(v.z + bs[kb + 2], 0.f);
                v.w = fmaxf(v.w + bs[kb + 3], 0.f);
            }
            float* p = Xs + r * XS + kq * 8;
            *(float2*)(p + 0) = make_float2(v.x, v.x);
            *(float2*)(p + 2) = make_float2(v.y, v.y);
            *(float2*)(p + 4) = make_float2(v.z, v.z);
            *(float2*)(p + 6) = make_float2(v.w, v.w);
        }
        __syncthreads();

        const float* Xr = Xs + (rg * 8) * XS;
        #pragma unroll
        for (int kk = 0; kk < KT / 2; kk++) {
            unsigned long long w0xy = *(const unsigned long long*)(Ws + (2 * kk) * 64 + cg * 4);
            unsigned long long w0zw = *(const unsigned long long*)(Ws + (2 * kk) * 64 + cg * 4 + 2);
            unsigned long long w1xy = *(const unsigned long long*)(Ws + (2 * kk + 1) * 64 + cg * 4);
            unsigned long long w1zw = *(const unsigned long long*)(Ws + (2 * kk + 1) * 64 + cg * 4 + 2);
            #pragma unroll
            for (int j = 0; j < 8; j++) {
                ulonglong2 xd = *(const ulonglong2*)(Xr + j * XS + kk * 4);
                ffma2(axy[j], xd.x, w0xy);
                ffma2(azw[j], xd.x, w0zw);
                ffma2(axy[j], xd.y, w1xy);
                ffma2(azw[j], xd.y, w1zw);
            }
        }
    }

    #pragma unroll
    for (int j = 0; j < 8; j++) {
        int gr = row0 + rg * 8 + j;
        if (gr < N) {
            float2 lo = *(float2*)&axy[j];
            float2 hi = *(float2*)&azw[j];
            __nv_bfloat162 b0 = __float22bfloat162_rn(lo);
            __nv_bfloat162 b1 = __float22bfloat162_rn(hi);
            uint2 pk;
            pk.x = *(unsigned*)&b0;
            pk.y = *(unsigned*)&b1;
            out[(long long)gr * 16 + cg] = pk;
        }
    }
}

// ---------------------------------------------------------------------------
// Aggregate from bf16 h (R5-proven). Warp per node; 4 groups of 8 lanes.
// EPI==1: fuse +b2 and log_softmax.
// ---------------------------------------------------------------------------
template <int EPI>
__global__ void k_agg(const uint4* __restrict__ h, float* __restrict__ out,
                      const float* __restrict__ bias, int N) {
    int node = blockIdx.x * 8 + (threadIdx.x >> 5);
    if (node >= N) return;
    int lane = threadIdx.x & 31;
    int grp = lane >> 3;
    int gl  = lane & 7;
    int beg = g_off[node];
    int end = g_off[node + 1];

    float2 acc[4];
    #pragma unroll
    for (int i = 0; i < 4; i++) acc[i] = make_float2(0.f, 0.f);

    #pragma unroll 2
    for (int j = beg + grp; j < end; j += 4) {
        float2 r = g_rec[j];
        int s = __float_as_int(r.x);
        uint4 v = __ldg(h + (long long)s * 8 + gl);
        float2 f;
        f = __bfloat1622float2(*(__nv_bfloat162*)&v.x);
        acc[0].x += f.x * r.y; acc[0].y += f.y * r.y;
        f = __bfloat1622float2(*(__nv_bfloat162*)&v.y);
        acc[1].x += f.x * r.y; acc[1].y += f.y * r.y;
        f = __bfloat1622float2(*(__nv_bfloat162*)&v.z);
        acc[2].x += f.x * r.y; acc[2].y += f.y * r.y;
        f = __bfloat1622float2(*(__nv_bfloat162*)&v.w);
        acc[3].x += f.x * r.y; acc[3].y += f.y * r.y;
    }
    #pragma unroll
    for (int i = 0; i < 4; i++) {
        acc[i].x += __shfl_xor_sync(0xffffffffu, acc[i].x, 8);
        acc[i].y += __shfl_xor_sync(0xffffffffu, acc[i].y, 8);
        acc[i].x += __shfl_xor_sync(0xffffffffu, acc[i].x, 16);
        acc[i].y += __shfl_xor_sync(0xffffffffu, acc[i].y, 16);
    }

    if (EPI == 0) {
        if (lane < 8) {
            float4* op = (float4*)(out + (long long)node * 64 + gl * 8);
            op[0] = make_float4(acc[0].x, acc[0].y, acc[1].x, acc[1].y);
            op[1] = make_float4(acc[2].x, acc[2].y, acc[3].x, acc[3].y);
        }
    } else {
        const float4* bp = (const float4*)(bias + gl * 8);
        float4 b0 = bp[0], b1 = bp[1];
        acc[0].x += b0.x; acc[0].y += b0.y; acc[1].x += b0.z; acc[1].y += b0.w;
        acc[2].x += b1.x; acc[2].y += b1.y; acc[3].x += b1.z; acc[3].y += b1.w;
        float m = fmaxf(fmaxf(fmaxf(acc[0].x, acc[0].y), fmaxf(acc[1].x, acc[1].y)),
                        fmaxf(fmaxf(acc[2].x, acc[2].y), fmaxf(acc[3].x, acc[3].y)));
        #pragma unroll
        for (int o = 1; o < 8; o <<= 1)
            m = fmaxf(m, __shfl_xor_sync(0xffffffffu, m, o));
        float s = expf(acc[0].x - m) + expf(acc[0].y - m)
                + expf(acc[1].x - m) + expf(acc[1].y - m)
                + expf(acc[2].x - m) + expf(acc[2].y - m)
                + expf(acc[3].x - m) + expf(acc[3].y - m);
        #pragma unroll
        for (int o = 1; o < 8; o <<= 1)
            s += __shfl_xor_sync(0xffffffffu, s, o);
        float lse = m + logf(s);
        if (lane < 8) {
            float4* op = (float4*)(out + (long long)node * 64 + gl * 8);
            op[0] = make_float4(acc[0].x - lse, acc[0].y - lse,
                                acc[1].x - lse, acc[1].y - lse);
            op[1] = make_float4(acc[2].x - lse, acc[2].y - lse,
                                acc[3].x - lse, acc[3].y - lse);
        }
    }
}

// ---------------------------------------------------------------------------
extern "C" void kernel_launch(void* const* d_in, const int* in_sizes, int n_in,
                              void* d_out, int out_size) {
    const float* x  = (const float*)d_in[0];
    const void*  ei = d_in[1];
    const float* W1 = (const float*)d_in[2];
    const float* b1 = (const float*)d_in[3];
    const float* W2 = (const float*)d_in[4];
    const float* b2 = (const float*)d_in[5];
    float* out = (float*)d_out;

    int N = in_sizes[0] / 128;                 // 100000
    long long E = (long long)in_sizes[1] / 2;  // 1600000
    long long M = E + (long long)N;

    static cudaStream_t s2 = nullptr;
    static cudaEvent_t evFork = nullptr, evJoin = nullptr;
    if (!s2) {
        cudaStreamCreateWithFlags(&s2, cudaStreamNonBlocking);
        cudaEventCreateWithFlags(&evFork, cudaEventDisableTiming);
        cudaEventCreateWithFlags(&evJoin, cudaEventDisableTiming);
        cudaFuncSetAttribute(k_gemm1_mma,
                             cudaFuncAttributeMaxDynamicSharedMemorySize,
                             G1_SMEM_TOT);
    }

    uint4* ph;
    float* pagg;
    cudaGetSymbolAddress((void**)&ph, g_h);
    cudaGetSymbolAddress((void**)&pagg, g_agg);

    int bN    = (N + 255) / 256;
    int bDeg  = (int)((E + 255) / 256);
    int bMsg  = (int)((M + 255) / 256);
    int bGemm = (N + 127) / 128;
    int bAgg  = (N + 7) / 8;

    // Fork: HMMA GEMM1 (x,W1 only) on s2, concurrent with CSR prep.
    cudaEventRecord(evFork, 0);
    cudaStreamWaitEvent(s2, evFork, 0);
    k_gemm1_mma<<<bGemm, 256, G1_SMEM_TOT, s2>>>(x, W1, (unsigned*)ph, N);
    cudaEventRecord(evJoin, s2);

    k_init<<<bN, 256>>>(ei, N);
    k_count<<<bDeg, 256>>>(ei, E);
    k_scan1<<<bN, 256>>>(N);
    k_scan2<<<1, 512>>>(bN);
    k_scan3<<<bN, 256>>>(N);
    k_place<<<bMsg, 256>>>(ei, E, N);

    // Join: aggregation needs both g_h (s2) and g_rec (default)
    cudaStreamWaitEvent(0, evJoin, 0);

    // layer 1 aggregate (fp32 out)
    k_agg<0><<<bAgg, 256>>>(ph, pagg, nullptr, N);

    // layer 2: h2 = relu(agg1 + b1) @ W2 (bf16 out, overwrites g_h; agg0 done)
    k_gemm<64, 1><<<bGemm, 256>>>(pagg, W2, b1, (uint2*)ph, N);

    // final aggregate + b2 + log_softmax
    k_agg<1><<<bAgg, 256>>>(ph, out, b2, N);
}

// round 12
// speedup vs baseline: 1.4413x; 1.0784x over previous
#include <cuda_runtime.h>
#include <cuda_bf16.h>
#include <math.h>
#include <stdint.h>

// Fixed problem shape (from setup_inputs): N=100000, E=1600000, F_IN=128, H=C=64
#define NNODES 100000
#define HD 64
#define MSGMAX 1800000   // E + N with headroom

// Scratch (allocation-free: __device__ globals)
__device__ int    g_cnt[NNODES];            // per-dst message count (incl. self-loop)
__device__ int    g_off[NNODES + 1];        // CSR offsets
__device__ int    g_cur[NNODES];            // placement cursors
__device__ int    g_bsum[512];              // block sums for scan
__device__ int    g_boff[512];              // block offsets for scan
__device__ float2 g_rec[MSGMAX];            // per-message {src_bits, norm}
__device__ uint4  g_h[NNODES * 8];          // GEMM output in bf16 (64 bf16 = 8 uint4/row)
__device__ float  g_agg[NNODES * HD];       // layer-1 aggregate (fp32)
__device__ int    g_is64;                   // edge_index dtype flag

__device__ __forceinline__ long long load_edge(const void* ei, long long pos) {
    if (g_is64) return ((const long long*)ei)[pos];
    return (long long)((const int*)ei)[pos];
}

// ---------------------------------------------------------------------------
// init: cnt = 1 (self loop), detect index width
// ---------------------------------------------------------------------------
__global__ void k_init(const void* ei, int N) {
    int i = blockIdx.x * 256 + threadIdx.x;
    if (i < N) g_cnt[i] = 1;
    if (i == 0) {
        const unsigned long long* p = (const unsigned long long*)ei;
        int ok = 1;
        #pragma unroll 4
        for (int j = 0; j < 64; j++)
            if (p[j] >= (unsigned long long)N) ok = 0;
        g_is64 = ok;
    }
}

// ---------------------------------------------------------------------------
// degree count over dst
// ---------------------------------------------------------------------------
__global__ void k_count(const void* ei, long long E) {
    long long e = (long long)blockIdx.x * 256 + threadIdx.x;
    if (e < E) {
        int d = (int)load_edge(ei, E + e);
        atomicAdd(&g_cnt[d], 1);
    }
}

// ---------------------------------------------------------------------------
// 3-phase exclusive scan of g_cnt -> g_off  (R5-proven)
// ---------------------------------------------------------------------------
__global__ void k_scan1(int N) {
    __shared__ int s[256];
    int i = blockIdx.x * 256 + threadIdx.x;
    int v = (i < N) ? g_cnt[i] : 0;
    s[threadIdx.x] = v;
    __syncthreads();
    #pragma unroll
    for (int o = 128; o > 0; o >>= 1) {
        if (threadIdx.x < o) s[threadIdx.x] += s[threadIdx.x + o];
        __syncthreads();
    }
    if (threadIdx.x == 0) g_bsum[blockIdx.x] = s[0];
}

__global__ void k_scan2(int nb) {
    __shared__ int wsum[16];
    int t = threadIdx.x;
    int lane = t & 31;
    int w = t >> 5;
    int v = (t < nb) ? g_bsum[t] : 0;
    int x = v;
    #pragma unroll
    for (int o = 1; o < 32; o <<= 1) {
        int y = __shfl_up_sync(0xffffffffu, x, o);
        if (lane >= o) x += y;
    }
    if (lane == 31) wsum[w] = x;
    __syncthreads();
    if (w == 0) {
        int ws = (lane < 16) ? wsum[lane] : 0;
        #pragma unroll
        for (int o = 1; o < 16; o <<= 1) {
            int y = __shfl_up_sync(0xffffffffu, ws, o);
            if (lane >= o) ws += y;
        }
        if (lane < 16) wsum[lane] = ws;
    }
    __syncthreads();
    int base = (w > 0) ? wsum[w - 1] : 0;
    if (t < nb) g_boff[t] = base + x - v;
}

__global__ void k_scan3(int N) {
    __shared__ int s[256];
    int i = blockIdx.x * 256 + threadIdx.x;
    int v = (i < N) ? g_cnt[i] : 0;
    s[threadIdx.x] = v;
    __syncthreads();
    #pragma unroll
    for (int o = 1; o < 256; o <<= 1) {
        int tv = (threadIdx.x >= o) ? s[threadIdx.x - o] : 0;
        __syncthreads();
        s[threadIdx.x] += tv;
        __syncthreads();
    }
    if (i < N) {
        int off = g_boff[blockIdx.x] + s[threadIdx.x] - v;
        g_off[i] = off;
        g_cur[i] = off;
        if (i == N - 1) g_off[N] = off + v;
    }
}

// ---------------------------------------------------------------------------
// place: bucket message records {src, rsqrt(deg_s*deg_d)} by dst
// ---------------------------------------------------------------------------
__global__ void k_place(const void* ei, long long E, int N) {
    long long e = (long long)blockIdx.x * 256 + threadIdx.x;
    long long M = E + (long long)N;
    if (e >= M) return;
    int s, d;
    if (e < E) {
        s = (int)load_edge(ei, e);
        d = (int)load_edge(ei, E + e);
    } else {
        s = d = (int)(e - E);
    }
    float nrm = rsqrtf((float)(g_cnt[s] * g_cnt[d]));
    int pos = atomicAdd(&g_cur[d], 1);
    g_rec[pos] = make_float2(__int_as_float(s), nrm);
}

// ---------------------------------------------------------------------------
// GEMM1 via mma.sync bf16 HMMA (proven R11).
// CTA: 128 rows x 64 cols x K=128. 8 warps, warp tile m16 x n64.
// ---------------------------------------------------------------------------
#define G1_XSTRIDE 136                    // bf16 units per X smem row
#define G1_XS_BYTES (128 * G1_XSTRIDE * 2)   // 34816
#define G1_WF_OFF   G1_XS_BYTES
#define G1_SMEM_TOT (G1_XS_BYTES + 8 * 8 * 32 * 8)   // + 16384 = 51200

__global__ __launch_bounds__(256)
void k_gemm1_mma(const float* __restrict__ X, const float* __restrict__ W,
                 unsigned* __restrict__ out, int N) {
    extern __shared__ char smem[];
    __nv_bfloat16* Xs = (__nv_bfloat16*)smem;
    uint2* Wf = (uint2*)(smem + G1_WF_OFF);

    int tid = threadIdx.x;
    int wid = tid >> 5, lane = tid & 31;
    int tig = lane & 3, gid = lane >> 2;
    int row0 = blockIdx.x * 128;

    // Pack W fragments: Wf[(ks*8+nt)*32 + lane] = {bf16x2(b0,b1), bf16x2(b2,b3)}
    for (int idx = tid; idx < 2048; idx += 256) {
        int l = idx & 31;
        int nt = (idx >> 5) & 7;
        int ks = idx >> 8;
        int lt = l & 3, lg = l >> 2;
        int k0 = ks * 16 + lt * 2;
        int n  = nt * 8 + lg;
        float b0 = W[(long long)k0 * 64 + n];
        float b1 = W[(long long)(k0 + 1) * 64 + n];
        float b2 = W[(long long)(k0 + 8) * 64 + n];
        float b3 = W[(long long)(k0 + 9) * 64 + n];
        __nv_bfloat162 p0 = __float22bfloat162_rn(make_float2(b0, b1));
        __nv_bfloat162 p1 = __float22bfloat162_rn(make_float2(b2, b3));
        Wf[idx] = make_uint2(*(unsigned*)&p0, *(unsigned*)&p1);
    }

    // X tile fp32 -> bf16 smem (coalesced float4 reads)
    for (int idx = tid; idx < 128 * 32; idx += 256) {
        int r  = idx >> 5;
        int c4 = idx & 31;
        int gr = row0 + r;
        float4 v = make_float4(0.f, 0.f, 0.f, 0.f);
        if (gr < N) v = *(const float4*)(X + (long long)gr * 128 + c4 * 4);
        __nv_bfloat162 p0 = __float22bfloat162_rn(make_float2(v.x, v.y));
        __nv_bfloat162 p1 = __float22bfloat162_rn(make_float2(v.z, v.w));
        *(uint2*)((char*)Xs + ((long long)r * G1_XSTRIDE + c4 * 4) * 2) =
            make_uint2(*(unsigned*)&p0, *(unsigned*)&p1);
    }
    __syncthreads();

    float acc[8][4];
    #pragma unroll
    for (int nt = 0; nt < 8; nt++)
        #pragma unroll
        for (int q = 0; q < 4; q++) acc[nt][q] = 0.f;

    int rw = wid * 16;
    const char* XsB = (const char*)Xs;

    #pragma unroll
    for (int ks = 0; ks < 8; ks++) {
        int cbase = ks * 16 + tig * 2;
        unsigned A0 = *(const unsigned*)(XsB + ((rw + gid)     * G1_XSTRIDE + cbase)     * 2);
        unsigned A1 = *(const unsigned*)(XsB + ((rw + gid + 8) * G1_XSTRIDE + cbase)     * 2);
        unsigned A2 = *(const unsigned*)(XsB + ((rw + gid)     * G1_XSTRIDE + cbase + 8) * 2);
        unsigned A3 = *(const unsigned*)(XsB + ((rw + gid + 8) * G1_XSTRIDE + cbase + 8) * 2);
        #pragma unroll
        for (int nt = 0; nt < 8; nt++) {
            uint2 bb = Wf[(ks * 8 + nt) * 32 + lane];
            asm volatile(
                "mma.sync.aligned.m16n8k16.row.col.f32.bf16.bf16.f32 "
                "{%0,%1,%2,%3}, {%4,%5,%6,%7}, {%8,%9}, {%0,%1,%2,%3};"
                : "+f"(acc[nt][0]), "+f"(acc[nt][1]),
                  "+f"(acc[nt][2]), "+f"(acc[nt][3])
                : "r"(A0), "r"(A1), "r"(A2), "r"(A3),
                  "r"(bb.x), "r"(bb.y));
        }
    }

    int gr0 = row0 + rw + gid;
    int gr1 = gr0 + 8;
    #pragma unroll
    for (int nt = 0; nt < 8; nt++) {
        int cw = nt * 4 + tig;
        if (gr0 < N) {
            __nv_bfloat162 p = __float22bfloat162_rn(
                make_float2(acc[nt][0], acc[nt][1]));
            out[(long long)gr0 * 32 + cw] = *(unsigned*)&p;
        }
        if (gr1 < N) {
            __nv_bfloat162 p = __float22bfloat162_rn(
                make_float2(acc[nt][2], acc[nt][3]));
            out[(long long)gr1 * 32 + cw] = *(unsigned*)&p;
        }
    }
}

// ---------------------------------------------------------------------------
// GEMM2 via mma.sync bf16 HMMA: out[N,64](bf16) = relu(agg[N,64]+b1) @ W2.
// Same warp-tile recipe as GEMM1 with K=64 (4 k-steps). Bias+ReLU fused into
// the X-tile load (bias via __ldg, no extra sync). Static smem 26.6 KB.
// X stride 72 bf16 = 144 B = 36 banks (== 4 mod 32): A-frag loads conflict-
// free, bank = 4*gid + tig.
// ---------------------------------------------------------------------------
#define G2_XSTRIDE 72

__global__ __launch_bounds__(256)
void k_gemm2_mma(const float* __restrict__ X, const float* __restrict__ W,
                 const float* __restrict__ bias, unsigned* __restrict__ out,
                 int N) {
    __shared__ __nv_bfloat16 Xs[128 * G2_XSTRIDE];   // 18432 B
    __shared__ uint2 Wf[4 * 8 * 32];                 // 8192 B

    int tid = threadIdx.x;
    int wid = tid >> 5, lane = tid & 31;
    int tig = lane & 3, gid = lane >> 2;
    int row0 = blockIdx.x * 128;

    // Pack W2 fragments (K=64 -> ks 0..3)
    for (int idx = tid; idx < 1024; idx += 256) {
        int l = idx & 31;
        int nt = (idx >> 5) & 7;
        int ks = idx >> 8;
        int lt = l & 3, lg = l >> 2;
        int k0 = ks * 16 + lt * 2;
        int n  = nt * 8 + lg;
        float b0 = W[(long long)k0 * 64 + n];
        float b1 = W[(long long)(k0 + 1) * 64 + n];
        float b2 = W[(long long)(k0 + 8) * 64 + n];
        float b3 = W[(long long)(k0 + 9) * 64 + n];
        __nv_bfloat162 p0 = __float22bfloat162_rn(make_float2(b0, b1));
        __nv_bfloat162 p1 = __float22bfloat162_rn(make_float2(b2, b3));
        Wf[idx] = make_uint2(*(unsigned*)&p0, *(unsigned*)&p1);
    }

    // X tile: fp32 agg -> relu(+b1) -> bf16 smem.  128 rows x 16 float4.
    for (int idx = tid; idx < 128 * 16; idx += 256) {
        int r  = idx >> 4;
        int c4 = idx & 15;
        int gr = row0 + r;
        float4 v = make_float4(0.f, 0.f, 0.f, 0.f);
        if (gr < N) {
            v = *(const float4*)(X + (long long)gr * 64 + c4 * 4);
            float4 bv = __ldg((const float4*)bias + c4);
            v.x = fmaxf(v.x + bv.x, 0.f);
            v.y = fmaxf(v.y + bv.y, 0.f);
            v.z = fmaxf(v.z + bv.z, 0.f);
            v.w = fmaxf(v.w + bv.w, 0.f);
        }
        __nv_bfloat162 p0 = __float22bfloat162_rn(make_float2(v.x, v.y));
        __nv_bfloat162 p1 = __float22bfloat162_rn(make_float2(v.z, v.w));
        *(uint2*)((char*)Xs + ((long long)r * G2_XSTRIDE + c4 * 4) * 2) =
            make_uint2(*(unsigned*)&p0, *(unsigned*)&p1);
    }
    __syncthreads();

    float acc[8][4];
    #pragma unroll
    for (int nt = 0; nt < 8; nt++)
        #pragma unroll
        for (int q = 0; q < 4; q++) acc[nt][q] = 0.f;

    int rw = wid * 16;
    const char* XsB = (const char*)Xs;

    #pragma unroll
    for (int ks = 0; ks < 4; ks++) {
        int cbase = ks * 16 + tig * 2;
        unsigned A0 = *(const unsigned*)(XsB + ((rw + gid)     * G2_XSTRIDE + cbase)     * 2);
        unsigned A1 = *(const unsigned*)(XsB + ((rw + gid + 8) * G2_XSTRIDE + cbase)     * 2);
        unsigned A2 = *(const unsigned*)(XsB + ((rw + gid)     * G2_XSTRIDE + cbase + 8) * 2);
        unsigned A3 = *(const unsigned*)(XsB + ((rw + gid + 8) * G2_XSTRIDE + cbase + 8) * 2);
        #pragma unroll
        for (int nt = 0; nt < 8; nt++) {
            uint2 bb = Wf[(ks * 8 + nt) * 32 + lane];
            asm volatile(
                "mma.sync.aligned.m16n8k16.row.col.f32.bf16.bf16.f32 "
                "{%0,%1,%2,%3}, {%4,%5,%6,%7}, {%8,%9}, {%0,%1,%2,%3};"
                : "+f"(acc[nt][0]), "+f"(acc[nt][1]),
                  "+f"(acc[nt][2]), "+f"(acc[nt][3])
                : "r"(A0), "r"(A1), "r"(A2), "r"(A3),
                  "r"(bb.x), "r"(bb.y));
        }
    }

    int gr0 = row0 + rw + gid;
    int gr1 = gr0 + 8;
    #pragma unroll
    for (int nt = 0; nt < 8; nt++) {
        int cw = nt * 4 + tig;
        if (gr0 < N) {
            __nv_bfloat162 p = __float22bfloat162_rn(
                make_float2(acc[nt][0], acc[nt][1]));
            out[(long long)gr0 * 32 + cw] = *(unsigned*)&p;
        }
        if (gr1 < N) {
            __nv_bfloat162 p = __float22bfloat162_rn(
                make_float2(acc[nt][2], acc[nt][3]));
            out[(long long)gr1 * 32 + cw] = *(unsigned*)&p;
        }
    }
}

// ---------------------------------------------------------------------------
// Aggregate from bf16 h (R5-proven). Warp per node; 4 groups of 8 lanes.
// EPI==1: fuse +b2 and log_softmax.
// ---------------------------------------------------------------------------
template <int EPI>
__global__ void k_agg(const uint4* __restrict__ h, float* __restrict__ out,
                      const float* __restrict__ bias, int N) {
    int node = blockIdx.x * 8 + (threadIdx.x >> 5);
    if (node >= N) return;
    int lane = threadIdx.x & 31;
    int grp = lane >> 3;
    int gl  = lane & 7;
    int beg = g_off[node];
    int end = g_off[node + 1];

    float2 acc[4];
    #pragma unroll
    for (int i = 0; i < 4; i++) acc[i] = make_float2(0.f, 0.f);

    #pragma unroll 2
    for (int j = beg + grp; j < end; j += 4) {
        float2 r = g_rec[j];
        int s = __float_as_int(r.x);
        uint4 v = __ldg(h + (long long)s * 8 + gl);
        float2 f;
        f = __bfloat1622float2(*(__nv_bfloat162*)&v.x);
        acc[0].x += f.x * r.y; acc[0].y += f.y * r.y;
        f = __bfloat1622float2(*(__nv_bfloat162*)&v.y);
        acc[1].x += f.x * r.y; acc[1].y += f.y * r.y;
        f = __bfloat1622float2(*(__nv_bfloat162*)&v.z);
        acc[2].x += f.x * r.y; acc[2].y += f.y * r.y;
        f = __bfloat1622float2(*(__nv_bfloat162*)&v.w);
        acc[3].x += f.x * r.y; acc[3].y += f.y * r.y;
    }
    #pragma unroll
    for (int i = 0; i < 4; i++) {
        acc[i].x += __shfl_xor_sync(0xffffffffu, acc[i].x, 8);
        acc[i].y += __shfl_xor_sync(0xffffffffu, acc[i].y, 8);
        acc[i].x += __shfl_xor_sync(0xffffffffu, acc[i].x, 16);
        acc[i].y += __shfl_xor_sync(0xffffffffu, acc[i].y, 16);
    }

    if (EPI == 0) {
        if (lane < 8) {
            float4* op = (float4*)(out + (long long)node * 64 + gl * 8);
            op[0] = make_float4(acc[0].x, acc[0].y, acc[1].x, acc[1].y);
            op[1] = make_float4(acc[2].x, acc[2].y, acc[3].x, acc[3].y);
        }
    } else {
        const float4* bp = (const float4*)(bias + gl * 8);
        float4 b0 = bp[0], b1 = bp[1];
        acc[0].x += b0.x; acc[0].y += b0.y; acc[1].x += b0.z; acc[1].y += b0.w;
        acc[2].x += b1.x; acc[2].y += b1.y; acc[3].x += b1.z; acc[3].y += b1.w;
        float m = fmaxf(fmaxf(fmaxf(acc[0].x, acc[0].y), fmaxf(acc[1].x, acc[1].y)),
                        fmaxf(fmaxf(acc[2].x, acc[2].y), fmaxf(acc[3].x, acc[3].y)));
        #pragma unroll
        for (int o = 1; o < 8; o <<= 1)
            m = fmaxf(m, __shfl_xor_sync(0xffffffffu, m, o));
        float s = expf(acc[0].x - m) + expf(acc[0].y - m)
                + expf(acc[1].x - m) + expf(acc[1].y - m)
                + expf(acc[2].x - m) + expf(acc[2].y - m)
                + expf(acc[3].x - m) + expf(acc[3].y - m);
        #pragma unroll
        for (int o = 1; o < 8; o <<= 1)
            s += __shfl_xor_sync(0xffffffffu, s, o);
        float lse = m + logf(s);
        if (lane < 8) {
            float4* op = (float4*)(out + (long long)node * 64 + gl * 8);
            op[0] = make_float4(acc[0].x - lse, acc[0].y - lse,
                                acc[1].x - lse, acc[1].y - lse);
            op[1] = make_float4(acc[2].x - lse, acc[2].y - lse,
                                acc[3].x - lse, acc[3].y - lse);
        }
    }
}

// ---------------------------------------------------------------------------
extern "C" void kernel_launch(void* const* d_in, const int* in_sizes, int n_in,
                              void* d_out, int out_size) {
    const float* x  = (const float*)d_in[0];
    const void*  ei = d_in[1];
    const float* W1 = (const float*)d_in[2];
    const float* b1 = (const float*)d_in[3];
    const float* W2 = (const float*)d_in[4];
    const float* b2 = (const float*)d_in[5];
    float* out = (float*)d_out;

    int N = in_sizes[0] / 128;                 // 100000
    long long E = (long long)in_sizes[1] / 2;  // 1600000
    long long M = E + (long long)N;

    static cudaStream_t s2 = nullptr;
    static cudaEvent_t evFork = nullptr, evJoin = nullptr;
    if (!s2) {
        cudaStreamCreateWithFlags(&s2, cudaStreamNonBlocking);
        cudaEventCreateWithFlags(&evFork, cudaEventDisableTiming);
        cudaEventCreateWithFlags(&evJoin, cudaEventDisableTiming);
        cudaFuncSetAttribute(k_gemm1_mma,
                             cudaFuncAttributeMaxDynamicSharedMemorySize,
                             G1_SMEM_TOT);
    }

    uint4* ph;
    float* pagg;
    cudaGetSymbolAddress((void**)&ph, g_h);
    cudaGetSymbolAddress((void**)&pagg, g_agg);

    int bN    = (N + 255) / 256;
    int bDeg  = (int)((E + 255) / 256);
    int bMsg  = (int)((M + 255) / 256);
    int bGemm = (N + 127) / 128;
    int bAgg  = (N + 7) / 8;

    // Fork: HMMA GEMM1 (x,W1 only) on s2, concurrent with CSR prep.
    cudaEventRecord(evFork, 0);
    cudaStreamWaitEvent(s2, evFork, 0);
    k_gemm1_mma<<<bGemm, 256, G1_SMEM_TOT, s2>>>(x, W1, (unsigned*)ph, N);
    cudaEventRecord(evJoin, s2);

    k_init<<<bN, 256>>>(ei, N);
    k_count<<<bDeg, 256>>>(ei, E);
    k_scan1<<<bN, 256>>>(N);
    k_scan2<<<1, 512>>>(bN);
    k_scan3<<<bN, 256>>>(N);
    k_place<<<bMsg, 256>>>(ei, E, N);

    // Join: aggregation needs both g_h (s2) and g_rec (default)
    cudaStreamWaitEvent(0, evJoin, 0);

    // layer 1 aggregate (fp32 out)
    k_agg<0><<<bAgg, 256>>>(ph, pagg, nullptr, N);

    // layer 2: h2 = relu(agg1 + b1) @ W2 via HMMA (bf16 out, overwrites g_h)
    k_gemm2_mma<<<bGemm, 256>>>(pagg, W2, b1, (unsigned*)ph, N);

    // final aggregate + b2 + log_softmax
    k_agg<1><<<bAgg, 256>>>(ph, out, b2, N);
}